// round 1
// baseline (speedup 1.0000x reference)
#include <cuda_runtime.h>
#include <math_constants.h>

// Problem constants
constexpr int B = 4;
constexpr int T = 2048;
constexpr int D = 1024;
constexpr int H = 16;
constexpr int HD = 64;
constexpr int MTOK = B * T;          // 8192 token rows

// Scratch (allocation-free: __device__ globals)
__device__ float g_Q[(size_t)MTOK * D];
__device__ float g_K[(size_t)MTOK * D];
__device__ float g_V[(size_t)MTOK * D];
__device__ float g_AO[(size_t)MTOK * D];

// ---------------------------------------------------------------------------
// C[m,n] = sum_k A[m,k] * Bw[n,k] (+ bias[n])
// Both operands K-contiguous ("NT" gemm). 64x64 tile, BK=16, 256 threads,
// 4x4 register micro-tile per thread.
// ---------------------------------------------------------------------------
__global__ void __launch_bounds__(256) gemm_nt(const float* __restrict__ A,
                                               const float* __restrict__ Bw,
                                               const float* __restrict__ bias,
                                               float* __restrict__ C,
                                               int M, int N, int K)
{
    __shared__ __align__(16) float As[16][68];   // [k][m], stride 68 keeps 16B alignment
    __shared__ __align__(16) float Bs[16][68];   // [k][n]

    const int bm = blockIdx.y * 64;
    const int bn = blockIdx.x * 64;
    const int tid = threadIdx.x;
    const int lr = tid >> 2;            // 0..63 row within tile
    const int lk = (tid & 3) << 2;      // 0,4,8,12 k-offset
    const int tx = tid & 15;            // micro-tile col group
    const int ty = tid >> 4;            // micro-tile row group

    const float* Ap = A + (size_t)(bm + lr) * K + lk;
    const float* Bp = Bw + (size_t)(bn + lr) * K + lk;

    float acc[4][4] = {};

    for (int k0 = 0; k0 < K; k0 += 16) {
        float4 a4 = *(const float4*)(Ap + k0);
        float4 b4 = *(const float4*)(Bp + k0);
        As[lk + 0][lr] = a4.x; As[lk + 1][lr] = a4.y;
        As[lk + 2][lr] = a4.z; As[lk + 3][lr] = a4.w;
        Bs[lk + 0][lr] = b4.x; Bs[lk + 1][lr] = b4.y;
        Bs[lk + 2][lr] = b4.z; Bs[lk + 3][lr] = b4.w;
        __syncthreads();
#pragma unroll
        for (int kk = 0; kk < 16; kk++) {
            float4 av = *(const float4*)&As[kk][ty << 2];
            float4 bv = *(const float4*)&Bs[kk][tx << 2];
            float a[4] = {av.x, av.y, av.z, av.w};
            float b[4] = {bv.x, bv.y, bv.z, bv.w};
#pragma unroll
            for (int i = 0; i < 4; i++)
#pragma unroll
                for (int j = 0; j < 4; j++)
                    acc[i][j] = fmaf(a[i], b[j], acc[i][j]);
        }
        __syncthreads();
    }

    float bb[4] = {0.f, 0.f, 0.f, 0.f};
    if (bias != nullptr) {
#pragma unroll
        for (int j = 0; j < 4; j++) bb[j] = bias[bn + (tx << 2) + j];
    }
#pragma unroll
    for (int i = 0; i < 4; i++) {
        float4 r4 = make_float4(acc[i][0] + bb[0], acc[i][1] + bb[1],
                                acc[i][2] + bb[2], acc[i][3] + bb[3]);
        *(float4*)(C + (size_t)(bm + (ty << 2) + i) * N + bn + (tx << 2)) = r4;
    }
}

// ---------------------------------------------------------------------------
// Flash attention (causal), fp32. One block per (b, h, 64-query tile).
// 256 threads, 4x4 micro-tiles. Online softmax. Tiles above the diagonal
// skipped entirely.
// ---------------------------------------------------------------------------
constexpr int ATTN_SMEM_BYTES = 4 * 64 * 68 * 4;  // Qs + Ks + Vs + Ps = 69632 B

__global__ void __launch_bounds__(256) attn_fwd(const float* __restrict__ Q,
                                                const float* __restrict__ K,
                                                const float* __restrict__ V,
                                                float* __restrict__ O)
{
    extern __shared__ __align__(16) float sm[];
    float* Qs = sm;                 // [d][r]  stride 68
    float* Ks = sm + 64 * 68;       // [d][c]
    float* Vs = sm + 2 * 64 * 68;   // [c][e]
    float* Ps = sm + 3 * 64 * 68;   // [r][c]

    const int qt = blockIdx.x;      // query tile (0..31)
    const int h  = blockIdx.y;
    const int b  = blockIdx.z;
    const int tid = threadIdx.x;
    const int tx = tid & 15;
    const int ty = tid >> 4;

    const size_t head_off = (size_t)(b * T) * D + h * HD;
    const float* qbase = Q + head_off + (size_t)qt * 64 * D;

    // Load Q tile transposed: Qs[d][r]
#pragma unroll
    for (int it = 0; it < 4; it++) {
        int f = tid + 256 * it;
        int r = f >> 4;
        int d4 = (f & 15) << 2;
        float4 q4 = *(const float4*)(qbase + (size_t)r * D + d4);
        Qs[(d4 + 0) * 68 + r] = q4.x;
        Qs[(d4 + 1) * 68 + r] = q4.y;
        Qs[(d4 + 2) * 68 + r] = q4.z;
        Qs[(d4 + 3) * 68 + r] = q4.w;
    }

    float m[4], l[4], o[4][4];
#pragma unroll
    for (int i = 0; i < 4; i++) {
        m[i] = -CUDART_INF_F;
        l[i] = 0.f;
#pragma unroll
        for (int j = 0; j < 4; j++) o[i][j] = 0.f;
    }

    const float SCALE = 0.125f;                     // 1/sqrt(64)
    const float L2E = 1.4426950408889634f;

    for (int jt = 0; jt <= qt; jt++) {
        __syncthreads();   // previous PV done before overwriting K/V
        // Load K tile transposed (Ks[d][c]) and V tile natural (Vs[c][e])
#pragma unroll
        for (int it = 0; it < 4; it++) {
            int f = tid + 256 * it;
            int r = f >> 4;
            int d4 = (f & 15) << 2;
            const size_t goff = head_off + (size_t)(jt * 64 + r) * D + d4;
            float4 k4 = *(const float4*)(K + goff);
            Ks[(d4 + 0) * 68 + r] = k4.x;
            Ks[(d4 + 1) * 68 + r] = k4.y;
            Ks[(d4 + 2) * 68 + r] = k4.z;
            Ks[(d4 + 3) * 68 + r] = k4.w;
            *(float4*)&Vs[r * 68 + d4] = *(const float4*)(V + goff);
        }
        __syncthreads();

        // S = Q Kᵀ (this thread: rows ty*4.., cols tx*4..)
        float s[4][4] = {};
#pragma unroll 16
        for (int d = 0; d < 64; d++) {
            float4 qv = *(const float4*)&Qs[d * 68 + (ty << 2)];
            float4 kv = *(const float4*)&Ks[d * 68 + (tx << 2)];
            float a[4] = {qv.x, qv.y, qv.z, qv.w};
            float c[4] = {kv.x, kv.y, kv.z, kv.w};
#pragma unroll
            for (int i = 0; i < 4; i++)
#pragma unroll
                for (int j = 0; j < 4; j++)
                    s[i][j] = fmaf(a[i], c[j], s[i][j]);
        }

        // Scale + causal mask (only diagonal tile needs masking)
        if (jt == qt) {
#pragma unroll
            for (int i = 0; i < 4; i++)
#pragma unroll
                for (int j = 0; j < 4; j++) {
                    int qg = (ty << 2) + i;
                    int kg = (tx << 2) + j;
                    s[i][j] = (kg > qg) ? -CUDART_INF_F : s[i][j] * SCALE;
                }
        } else {
#pragma unroll
            for (int i = 0; i < 4; i++)
#pragma unroll
                for (int j = 0; j < 4; j++) s[i][j] *= SCALE;
        }

        // Online softmax per row (16 threads share a row; reduce width 16)
#pragma unroll
        for (int i = 0; i < 4; i++) {
            float tm = fmaxf(fmaxf(s[i][0], s[i][1]), fmaxf(s[i][2], s[i][3]));
#pragma unroll
            for (int off = 8; off > 0; off >>= 1)
                tm = fmaxf(tm, __shfl_xor_sync(0xffffffffu, tm, off, 16));
            float mnew = fmaxf(m[i], tm);
            float corr = exp2f((m[i] - mnew) * L2E);
            float rs = 0.f;
#pragma unroll
            for (int j = 0; j < 4; j++) {
                float p = exp2f((s[i][j] - mnew) * L2E);
                s[i][j] = p;
                rs += p;
            }
#pragma unroll
            for (int off = 8; off > 0; off >>= 1)
                rs += __shfl_xor_sync(0xffffffffu, rs, off, 16);
            l[i] = l[i] * corr + rs;
            m[i] = mnew;
#pragma unroll
            for (int j = 0; j < 4; j++) o[i][j] *= corr;
            // store P row (float4, conflict-free)
            *(float4*)&Ps[((ty << 2) + i) * 68 + (tx << 2)] =
                make_float4(s[i][0], s[i][1], s[i][2], s[i][3]);
        }
        __syncthreads();

        // O += P V  (this thread: rows ty*4.., dims tx*4..)
#pragma unroll 16
        for (int c = 0; c < 64; c++) {
            float4 vv = *(const float4*)&Vs[c * 68 + (tx << 2)];
            float p0 = Ps[((ty << 2) + 0) * 68 + c];
            float p1 = Ps[((ty << 2) + 1) * 68 + c];
            float p2 = Ps[((ty << 2) + 2) * 68 + c];
            float p3 = Ps[((ty << 2) + 3) * 68 + c];
            o[0][0] = fmaf(p0, vv.x, o[0][0]); o[0][1] = fmaf(p0, vv.y, o[0][1]);
            o[0][2] = fmaf(p0, vv.z, o[0][2]); o[0][3] = fmaf(p0, vv.w, o[0][3]);
            o[1][0] = fmaf(p1, vv.x, o[1][0]); o[1][1] = fmaf(p1, vv.y, o[1][1]);
            o[1][2] = fmaf(p1, vv.z, o[1][2]); o[1][3] = fmaf(p1, vv.w, o[1][3]);
            o[2][0] = fmaf(p2, vv.x, o[2][0]); o[2][1] = fmaf(p2, vv.y, o[2][1]);
            o[2][2] = fmaf(p2, vv.z, o[2][2]); o[2][3] = fmaf(p2, vv.w, o[2][3]);
            o[3][0] = fmaf(p3, vv.x, o[3][0]); o[3][1] = fmaf(p3, vv.y, o[3][1]);
            o[3][2] = fmaf(p3, vv.z, o[3][2]); o[3][3] = fmaf(p3, vv.w, o[3][3]);
        }
    }

    // Epilogue: normalize and write [b, t, h*64 + e] layout
    float* obase = O + head_off + (size_t)qt * 64 * D;
#pragma unroll
    for (int i = 0; i < 4; i++) {
        float inv = 1.0f / l[i];
        float4 r4 = make_float4(o[i][0] * inv, o[i][1] * inv,
                                o[i][2] * inv, o[i][3] * inv);
        *(float4*)(obase + (size_t)((ty << 2) + i) * D + (tx << 2)) = r4;
    }
}

// ---------------------------------------------------------------------------
extern "C" void kernel_launch(void* const* d_in, const int* in_sizes, int n_in,
                              void* d_out, int out_size)
{
    (void)in_sizes; (void)n_in; (void)out_size;
    const float* x  = (const float*)d_in[0];
    const float* Wq = (const float*)d_in[1];
    const float* Wk = (const float*)d_in[2];
    const float* Wv = (const float*)d_in[3];
    const float* Wo = (const float*)d_in[4];
    const float* bo = (const float*)d_in[5];
    float* out = (float*)d_out;

    float *q, *k, *v, *ao;
    cudaGetSymbolAddress((void**)&q,  g_Q);
    cudaGetSymbolAddress((void**)&k,  g_K);
    cudaGetSymbolAddress((void**)&v,  g_V);
    cudaGetSymbolAddress((void**)&ao, g_AO);

    cudaFuncSetAttribute(attn_fwd, cudaFuncAttributeMaxDynamicSharedMemorySize,
                         ATTN_SMEM_BYTES);

    dim3 gb(D / 64, MTOK / 64);   // (16, 128)
    gemm_nt<<<gb, 256>>>(x, Wq, nullptr, q, MTOK, D, D);
    gemm_nt<<<gb, 256>>>(x, Wk, nullptr, k, MTOK, D, D);
    gemm_nt<<<gb, 256>>>(x, Wv, nullptr, v, MTOK, D, D);

    attn_fwd<<<dim3(T / 64, H, B), 256, ATTN_SMEM_BYTES>>>(q, k, v, ao);

    gemm_nt<<<gb, 256>>>(ao, Wo, bo, out, MTOK, D, D);
}

// round 3
// speedup vs baseline: 2.6019x; 2.6019x over previous
#include <cuda_runtime.h>
#include <cuda_bf16.h>
#include <cstdint>

// ===========================================================================
// Problem constants
// ===========================================================================
constexpr int B = 4;
constexpr int T = 2048;
constexpr int D = 1024;
constexpr int H = 16;
constexpr int MTOK = B * T;          // 8192 token rows
using bf16 = __nv_bfloat16;

// ===========================================================================
// Scratch (allocation-free: __device__ globals), all bf16 hi/lo split pairs
// ===========================================================================
__device__ bf16 g_xh[(size_t)MTOK * D],  g_xl[(size_t)MTOK * D];
__device__ bf16 g_qh[(size_t)MTOK * D],  g_ql[(size_t)MTOK * D];
__device__ bf16 g_kh[(size_t)MTOK * D],  g_kl[(size_t)MTOK * D];
__device__ bf16 g_vh[(size_t)MTOK * D],  g_vl[(size_t)MTOK * D];
__device__ bf16 g_aoh[(size_t)MTOK * D], g_aol[(size_t)MTOK * D];
__device__ bf16 g_wqh[(size_t)D * D], g_wql[(size_t)D * D];
__device__ bf16 g_wkh[(size_t)D * D], g_wkl[(size_t)D * D];
__device__ bf16 g_wvh[(size_t)D * D], g_wvl[(size_t)D * D];
__device__ bf16 g_woh[(size_t)D * D], g_wol[(size_t)D * D];

// ===========================================================================
// PTX helpers (all sm_80-compatible; NO tcgen05 — compute_100 PTX target)
// ===========================================================================
__device__ __forceinline__ uint32_t cvta_smem(const void* p) {
    uint32_t a;
    asm("{ .reg .u64 t; cvta.to.shared.u64 t, %1; cvt.u32.u64 %0, t; }"
        : "=r"(a) : "l"(p));
    return a;
}

__device__ __forceinline__ void cp16(uint32_t dst, const void* src) {
    asm volatile("cp.async.cg.shared.global [%0], [%1], 16;"
                 :: "r"(dst), "l"(src));
}
#define CP_COMMIT() asm volatile("cp.async.commit_group;" ::: "memory")
template <int N>
__device__ __forceinline__ void cp_wait() {
    asm volatile("cp.async.wait_group %0;" :: "n"(N) : "memory");
}

__device__ __forceinline__ void ldm4(uint32_t* r, uint32_t a) {
    asm volatile("ldmatrix.sync.aligned.m8n8.x4.shared.b16 {%0,%1,%2,%3}, [%4];"
                 : "=r"(r[0]), "=r"(r[1]), "=r"(r[2]), "=r"(r[3]) : "r"(a));
}
__device__ __forceinline__ void ldm4t(uint32_t* r, uint32_t a) {
    asm volatile("ldmatrix.sync.aligned.m8n8.x4.trans.shared.b16 {%0,%1,%2,%3}, [%4];"
                 : "=r"(r[0]), "=r"(r[1]), "=r"(r[2]), "=r"(r[3]) : "r"(a));
}

__device__ __forceinline__ void mma_bf16(float* c, const uint32_t* a,
                                         const uint32_t* b) {
    asm volatile(
        "mma.sync.aligned.m16n8k16.row.col.f32.bf16.bf16.f32 "
        "{%0,%1,%2,%3}, {%4,%5,%6,%7}, {%8,%9}, {%0,%1,%2,%3};"
        : "+f"(c[0]), "+f"(c[1]), "+f"(c[2]), "+f"(c[3])
        : "r"(a[0]), "r"(a[1]), "r"(a[2]), "r"(a[3]), "r"(b[0]), "r"(b[1]));
}

__device__ __forceinline__ float ex2f(float x) {
    float r;
    asm("ex2.approx.f32 %0, %1;" : "=f"(r) : "f"(x));
    return r;
}

// split a pair of fp32 into packed bf16 hi and bf16 lo registers
__device__ __forceinline__ void split2(float v0, float v1,
                                       uint32_t& hp, uint32_t& lp) {
    bf16 h0 = __float2bfloat16(v0);
    bf16 h1 = __float2bfloat16(v1);
    bf16 l0 = __float2bfloat16(v0 - __bfloat162float(h0));
    bf16 l1 = __float2bfloat16(v1 - __bfloat162float(h1));
    hp = ((uint32_t)__bfloat16_as_ushort(h1) << 16) | __bfloat16_as_ushort(h0);
    lp = ((uint32_t)__bfloat16_as_ushort(l1) << 16) | __bfloat16_as_ushort(l0);
}

__device__ __forceinline__ void store_split2(bf16* Hh, bf16* Hl, size_t idx,
                                             float v0, float v1) {
    uint32_t hp, lp;
    split2(v0, v1, hp, lp);
    *(uint32_t*)(Hh + idx) = hp;
    *(uint32_t*)(Hl + idx) = lp;
}

// ===========================================================================
// fp32 -> (bf16 hi, bf16 lo) split
// ===========================================================================
__global__ void __launch_bounds__(256) split_fp32(const float* __restrict__ in,
                                                  bf16* __restrict__ hi,
                                                  bf16* __restrict__ lo,
                                                  int n4) {
    int i = blockIdx.x * 256 + threadIdx.x;
    if (i >= n4) return;
    int idx = i << 2;
    float4 v = *(const float4*)(in + idx);
    store_split2(hi, lo, idx,     v.x, v.y);
    store_split2(hi, lo, idx + 2, v.z, v.w);
}

// ===========================================================================
// mma.sync split-bf16 GEMM: C[M,N] = A[M,K] * Bw[N,K]^T (+bias)
// A = Ah+Al, B = Bh+Bl; C = Ah*Bh + Ah*Bl + Al*Bh (fp32 mma accum).
// Fixed: N = K = 1024. Tile 128x128, BK = 32, 8 warps of 64x32.
// OUT_BF16: write bf16 hi/lo split; else fp32 (+bias).
// ===========================================================================
constexpr int BM = 128, BN = 128, BK = 32;
constexpr int KPADB = 80;                       // bytes per smem row (40 elems)
constexpr int ATILE = BM * KPADB;               // 10240
constexpr int STAGE = 4 * ATILE;                // 40960
constexpr int GEMM_SMEM = 2 * STAGE;            // 81920
constexpr int NC = D / BK;                      // 32

template <int OUT_BF16>
__global__ void __launch_bounds__(256) gemm_mma(
    const bf16* __restrict__ Ah, const bf16* __restrict__ Al,
    const bf16* __restrict__ Bh, const bf16* __restrict__ Bl,
    const float* __restrict__ bias,
    float* __restrict__ Cf, bf16* __restrict__ Ch, bf16* __restrict__ Cl)
{
    extern __shared__ __align__(16) char smraw[];
    const uint32_t sb0 = cvta_smem(smraw);
    const int tid = threadIdx.x, lane = tid & 31, w = tid >> 5;
    const int wm = w >> 2, wn = w & 3;
    const int bm = blockIdx.y * BM, bn = blockIdx.x * BN;
    const int g = lane >> 3, tr = lane & 7;

    const char* pAh = (const char*)Ah;
    const char* pAl = (const char*)Al;
    const char* pBh = (const char*)Bh;
    const char* pBl = (const char*)Bl;

    auto stage_load = [&](int c, int st) {
        const uint32_t sbs = sb0 + st * STAGE;
        const size_t koff = (size_t)c * (BK * 2);
#pragma unroll
        for (int i = 0; i < 2; i++) {
            int cid = tid + 256 * i;
            int r = cid >> 2, cc = cid & 3;
            uint32_t so = r * KPADB + cc * 16;
            size_t ga = (size_t)(bm + r) * 2048 + koff + cc * 16;
            size_t gb = (size_t)(bn + r) * 2048 + koff + cc * 16;
            cp16(sbs + so,             pAh + ga);
            cp16(sbs + ATILE + so,     pAl + ga);
            cp16(sbs + 2 * ATILE + so, pBh + gb);
            cp16(sbs + 3 * ATILE + so, pBl + gb);
        }
        CP_COMMIT();
    };

    float acc[4][4][4];
#pragma unroll
    for (int i = 0; i < 4; i++)
#pragma unroll
        for (int j = 0; j < 4; j++)
#pragma unroll
            for (int e = 0; e < 4; e++) acc[i][j][e] = 0.f;

    stage_load(0, 0);

    for (int c = 0; c < NC; c++) {
        const int st = c & 1;
        if (c + 1 < NC) { stage_load(c + 1, st ^ 1); cp_wait<1>(); }
        else            { cp_wait<0>(); }
        __syncthreads();
        const uint32_t sA = sb0 + st * STAGE;
        const uint32_t sB = sA + 2 * ATILE;
#pragma unroll
        for (int ks = 0; ks < 2; ks++) {
            uint32_t ah[4][4], al[4][4], bb[2][4];
            const uint32_t acol = (ks * 16 + (g >> 1) * 8) * 2;
            const uint32_t arow = (uint32_t)((g & 1) * 8 + tr);
#pragma unroll
            for (int mi = 0; mi < 4; mi++) {
                uint32_t ad = sA + (wm * 64 + mi * 16 + arow) * KPADB + acol;
                ldm4(ah[mi], ad);
                ldm4(al[mi], ad + ATILE);
            }
            const uint32_t bcol = (ks * 16 + (g & 1) * 8) * 2;
            const uint32_t brow = (uint32_t)((g >> 1) * 8 + tr);
#pragma unroll
            for (int nh = 0; nh < 2; nh++)
                ldm4(bb[nh], sB + (wn * 32 + nh * 16 + brow) * KPADB + bcol);
            // Ah*Bh and Al*Bh
#pragma unroll
            for (int mi = 0; mi < 4; mi++)
#pragma unroll
                for (int ni = 0; ni < 4; ni++) {
                    mma_bf16(acc[mi][ni], ah[mi], &bb[ni >> 1][(ni & 1) * 2]);
                    mma_bf16(acc[mi][ni], al[mi], &bb[ni >> 1][(ni & 1) * 2]);
                }
            // Bl, then Ah*Bl
#pragma unroll
            for (int nh = 0; nh < 2; nh++)
                ldm4(bb[nh], sB + ATILE + (wn * 32 + nh * 16 + brow) * KPADB + bcol);
#pragma unroll
            for (int mi = 0; mi < 4; mi++)
#pragma unroll
                for (int ni = 0; ni < 4; ni++)
                    mma_bf16(acc[mi][ni], ah[mi], &bb[ni >> 1][(ni & 1) * 2]);
        }
        __syncthreads();
    }

    // Epilogue
    const int r0 = lane >> 2, c0 = (lane & 3) * 2;
#pragma unroll
    for (int mi = 0; mi < 4; mi++) {
        const int gr = bm + wm * 64 + mi * 16 + r0;
#pragma unroll
        for (int ni = 0; ni < 4; ni++) {
            const int gc = bn + wn * 32 + ni * 8 + c0;
            float v0 = acc[mi][ni][0], v1 = acc[mi][ni][1];
            float v2 = acc[mi][ni][2], v3 = acc[mi][ni][3];
            if (OUT_BF16) {
                store_split2(Ch, Cl, (size_t)gr * D + gc, v0, v1);
                store_split2(Ch, Cl, (size_t)(gr + 8) * D + gc, v2, v3);
            } else {
                float2 r4a = make_float2(v0 + bias[gc], v1 + bias[gc + 1]);
                float2 r4b = make_float2(v2 + bias[gc], v3 + bias[gc + 1]);
                *(float2*)(Cf + (size_t)gr * D + gc) = r4a;
                *(float2*)(Cf + (size_t)(gr + 8) * D + gc) = r4b;
            }
        }
    }
}

// ===========================================================================
// Flash attention (causal) with mma.sync split-bf16.
// CTA: 128 queries x 1 head. 8 warps, each owns 16 query rows (full rows ->
// softmax reduces only within 4-lane quads). KV streamed 64 keys/step,
// double-buffered cp.async. P stays in registers (S cfrag == PV afrag).
// ===========================================================================
constexpr int APADB = 144;                       // 72 elems per smem row
constexpr int QTILE = 128 * APADB;               // 18432
constexpr int KTILE = 64 * APADB;                // 9216
constexpr int KVSTAGE = 4 * KTILE;               // 36864
constexpr int ATT_SMEM = 2 * QTILE + 2 * KVSTAGE;  // 110592

__global__ void __launch_bounds__(256) attn_mma(
    const bf16* __restrict__ Qh, const bf16* __restrict__ Ql,
    const bf16* __restrict__ Kh, const bf16* __restrict__ Kl,
    const bf16* __restrict__ Vh, const bf16* __restrict__ Vl,
    bf16* __restrict__ AOh, bf16* __restrict__ AOl)
{
    extern __shared__ __align__(16) char smraw[];
    const uint32_t sb = cvta_smem(smraw);
    const uint32_t sQ = sb;
    const int qt = blockIdx.x, h = blockIdx.y, b = blockIdx.z;
    const int tid = threadIdx.x, lane = tid & 31, w = tid >> 5;
    const int g = lane >> 3, tr = lane & 7;
    const size_t tok0 = (size_t)(b * T + qt * 128);
    const size_t hoff = (size_t)h * 128;        // byte col offset of head

    // Q tile load (both splits) — 1024 chunks/tile
#pragma unroll
    for (int i = 0; i < 4; i++) {
        int cid = tid + 256 * i;
        int r = cid >> 3, cc = cid & 7;
        uint32_t so = r * APADB + cc * 16;
        size_t go = (tok0 + r) * 2048 + hoff + cc * 16;
        cp16(sQ + so,         (const char*)Qh + go);
        cp16(sQ + QTILE + so, (const char*)Ql + go);
    }
    auto kv_load = [&](int j, int st) {
        uint32_t skv = sb + 2 * QTILE + st * KVSTAGE;
        size_t kt0 = (size_t)(b * T + j * 64);
#pragma unroll
        for (int i = 0; i < 2; i++) {
            int cid = tid + 256 * i;
            int r = cid >> 3, cc = cid & 7;
            uint32_t so = r * APADB + cc * 16;
            size_t go = (kt0 + r) * 2048 + hoff + cc * 16;
            cp16(skv + so,             (const char*)Kh + go);
            cp16(skv + KTILE + so,     (const char*)Kl + go);
            cp16(skv + 2 * KTILE + so, (const char*)Vh + go);
            cp16(skv + 3 * KTILE + so, (const char*)Vl + go);
        }
        CP_COMMIT();
    };
    kv_load(0, 0);    // groups: {Q + KV0}

    float accO[8][4];
#pragma unroll
    for (int f = 0; f < 8; f++)
#pragma unroll
        for (int e = 0; e < 4; e++) accO[f][e] = 0.f;
    float m0 = -1e30f, m1 = -1e30f, l0 = 0.f, l1 = 0.f;

    const int jmax = 2 * qt + 1;
    const int qg0 = qt * 128 + w * 16 + (lane >> 2);   // global q row (within T)
    const float SCALE = 0.125f;
    const float L2E = 1.4426950408889634f;

    for (int j = 0; j <= jmax; j++) {
        const int st = j & 1;
        if (j < jmax) { kv_load(j + 1, st ^ 1); cp_wait<1>(); }
        else          { cp_wait<0>(); }
        __syncthreads();
        const uint32_t sK = sb + 2 * QTILE + st * KVSTAGE;
        const uint32_t sV = sK + 2 * KTILE;

        // ---- S = Q K^T (3-term split) ----
        float s[8][4];
#pragma unroll
        for (int f = 0; f < 8; f++)
#pragma unroll
            for (int e = 0; e < 4; e++) s[f][e] = 0.f;

        const uint32_t qrow = (uint32_t)(w * 16 + (g & 1) * 8 + tr);
        const uint32_t brow = (uint32_t)((g >> 1) * 8 + tr);
#pragma unroll
        for (int ks = 0; ks < 4; ks++) {
            uint32_t qh[4], ql[4], bbv[4];
            uint32_t qaddr = sQ + qrow * APADB + (ks * 16 + (g >> 1) * 8) * 2;
            ldm4(qh, qaddr);
            ldm4(ql, qaddr + QTILE);
            const uint32_t bcol = (ks * 16 + (g & 1) * 8) * 2;
#pragma unroll
            for (int nh = 0; nh < 4; nh++) {
                uint32_t kaddr = sK + (nh * 16 + brow) * APADB + bcol;
                ldm4(bbv, kaddr);                // Kh
                mma_bf16(s[2 * nh],     qh, bbv);
                mma_bf16(s[2 * nh + 1], qh, bbv + 2);
                mma_bf16(s[2 * nh],     ql, bbv);
                mma_bf16(s[2 * nh + 1], ql, bbv + 2);
                ldm4(bbv, kaddr + KTILE);        // Kl
                mma_bf16(s[2 * nh],     qh, bbv);
                mma_bf16(s[2 * nh + 1], qh, bbv + 2);
            }
        }

        // ---- scale + causal mask ----
        const bool need_mask = (j >= 2 * qt);
#pragma unroll
        for (int f = 0; f < 8; f++) {
            const int kgb = j * 64 + f * 8 + (lane & 3) * 2;
#pragma unroll
            for (int e = 0; e < 4; e++) {
                const int kg = kgb + (e & 1);
                const int qg = qg0 + (e >> 1) * 8;
                float v = s[f][e] * SCALE;
                if (need_mask && kg > qg) v = -1e30f;
                s[f][e] = v;
            }
        }

        // ---- online softmax (quad-wide reductions) ----
        float mx0 = -1e30f, mx1 = -1e30f;
#pragma unroll
        for (int f = 0; f < 8; f++) {
            mx0 = fmaxf(mx0, fmaxf(s[f][0], s[f][1]));
            mx1 = fmaxf(mx1, fmaxf(s[f][2], s[f][3]));
        }
        mx0 = fmaxf(mx0, __shfl_xor_sync(0xffffffffu, mx0, 1));
        mx0 = fmaxf(mx0, __shfl_xor_sync(0xffffffffu, mx0, 2));
        mx1 = fmaxf(mx1, __shfl_xor_sync(0xffffffffu, mx1, 1));
        mx1 = fmaxf(mx1, __shfl_xor_sync(0xffffffffu, mx1, 2));
        const float mn0 = fmaxf(m0, mx0);
        const float mn1 = fmaxf(m1, mx1);
        const float cr0 = ex2f((m0 - mn0) * L2E);
        const float cr1 = ex2f((m1 - mn1) * L2E);
        float sum0 = 0.f, sum1 = 0.f;
#pragma unroll
        for (int f = 0; f < 8; f++) {
            float p0 = ex2f((s[f][0] - mn0) * L2E);
            float p1 = ex2f((s[f][1] - mn0) * L2E);
            float p2 = ex2f((s[f][2] - mn1) * L2E);
            float p3 = ex2f((s[f][3] - mn1) * L2E);
            s[f][0] = p0; s[f][1] = p1; s[f][2] = p2; s[f][3] = p3;
            sum0 += p0 + p1;
            sum1 += p2 + p3;
        }
        sum0 += __shfl_xor_sync(0xffffffffu, sum0, 1);
        sum0 += __shfl_xor_sync(0xffffffffu, sum0, 2);
        sum1 += __shfl_xor_sync(0xffffffffu, sum1, 1);
        sum1 += __shfl_xor_sync(0xffffffffu, sum1, 2);
        l0 = l0 * cr0 + sum0;
        l1 = l1 * cr1 + sum1;
        m0 = mn0; m1 = mn1;
#pragma unroll
        for (int f = 0; f < 8; f++) {
            accO[f][0] *= cr0; accO[f][1] *= cr0;
            accO[f][2] *= cr1; accO[f][3] *= cr1;
        }

        // ---- O += P V (P from registers, 3-term split) ----
#pragma unroll
        for (int k2 = 0; k2 < 4; k2++) {
            uint32_t afh[4], afl[4];
            split2(s[2 * k2][0],     s[2 * k2][1],     afh[0], afl[0]);
            split2(s[2 * k2][2],     s[2 * k2][3],     afh[1], afl[1]);
            split2(s[2 * k2 + 1][0], s[2 * k2 + 1][1], afh[2], afl[2]);
            split2(s[2 * k2 + 1][2], s[2 * k2 + 1][3], afh[3], afl[3]);
            const uint32_t vrow = (uint32_t)(k2 * 16 + (g & 1) * 8 + tr);
#pragma unroll
            for (int db = 0; db < 4; db++) {
                uint32_t vaddr = sV + vrow * APADB + (db * 16 + (g >> 1) * 8) * 2;
                uint32_t bbv[4];
                ldm4t(bbv, vaddr);               // Vh
                mma_bf16(accO[2 * db],     afh, bbv);
                mma_bf16(accO[2 * db + 1], afh, bbv + 2);
                mma_bf16(accO[2 * db],     afl, bbv);
                mma_bf16(accO[2 * db + 1], afl, bbv + 2);
                ldm4t(bbv, vaddr + KTILE);       // Vl
                mma_bf16(accO[2 * db],     afh, bbv);
                mma_bf16(accO[2 * db + 1], afh, bbv + 2);
            }
        }
        __syncthreads();   // protect KV stage before next prefetch overwrites
    }

    // ---- epilogue: normalize, bf16-split store ----
    const float inv0 = 1.f / l0;
    const float inv1 = 1.f / l1;
    const size_t r0g = tok0 + w * 16 + (lane >> 2);
    const int c0 = (lane & 3) * 2;
#pragma unroll
    for (int f = 0; f < 8; f++) {
        const int gc = h * 64 + f * 8 + c0;
        store_split2(AOh, AOl, r0g * D + gc,
                     accO[f][0] * inv0, accO[f][1] * inv0);
        store_split2(AOh, AOl, (r0g + 8) * D + gc,
                     accO[f][2] * inv1, accO[f][3] * inv1);
    }
}

// ===========================================================================
extern "C" void kernel_launch(void* const* d_in, const int* in_sizes, int n_in,
                              void* d_out, int out_size)
{
    (void)in_sizes; (void)n_in; (void)out_size;
    const float* x  = (const float*)d_in[0];
    const float* Wq = (const float*)d_in[1];
    const float* Wk = (const float*)d_in[2];
    const float* Wv = (const float*)d_in[3];
    const float* Wo = (const float*)d_in[4];
    const float* bo = (const float*)d_in[5];
    float* out = (float*)d_out;

    bf16 *xh, *xl, *qh, *ql, *kh, *kl, *vh, *vl, *aoh, *aol;
    bf16 *wqh, *wql, *wkh, *wkl, *wvh, *wvl, *woh, *wol;
    cudaGetSymbolAddress((void**)&xh,  g_xh);
    cudaGetSymbolAddress((void**)&xl,  g_xl);
    cudaGetSymbolAddress((void**)&qh,  g_qh);
    cudaGetSymbolAddress((void**)&ql,  g_ql);
    cudaGetSymbolAddress((void**)&kh,  g_kh);
    cudaGetSymbolAddress((void**)&kl,  g_kl);
    cudaGetSymbolAddress((void**)&vh,  g_vh);
    cudaGetSymbolAddress((void**)&vl,  g_vl);
    cudaGetSymbolAddress((void**)&aoh, g_aoh);
    cudaGetSymbolAddress((void**)&aol, g_aol);
    cudaGetSymbolAddress((void**)&wqh, g_wqh);
    cudaGetSymbolAddress((void**)&wql, g_wql);
    cudaGetSymbolAddress((void**)&wkh, g_wkh);
    cudaGetSymbolAddress((void**)&wkl, g_wkl);
    cudaGetSymbolAddress((void**)&wvh, g_wvh);
    cudaGetSymbolAddress((void**)&wvl, g_wvl);
    cudaGetSymbolAddress((void**)&woh, g_woh);
    cudaGetSymbolAddress((void**)&wol, g_wol);

    cudaFuncSetAttribute(gemm_mma<1>, cudaFuncAttributeMaxDynamicSharedMemorySize,
                         GEMM_SMEM);
    cudaFuncSetAttribute(gemm_mma<0>, cudaFuncAttributeMaxDynamicSharedMemorySize,
                         GEMM_SMEM);
    cudaFuncSetAttribute(attn_mma, cudaFuncAttributeMaxDynamicSharedMemorySize,
                         ATT_SMEM);

    const int nx4 = MTOK * D / 4;
    const int nw4 = D * D / 4;
    split_fp32<<<(nx4 + 255) / 256, 256>>>(x,  xh,  xl,  nx4);
    split_fp32<<<(nw4 + 255) / 256, 256>>>(Wq, wqh, wql, nw4);
    split_fp32<<<(nw4 + 255) / 256, 256>>>(Wk, wkh, wkl, nw4);
    split_fp32<<<(nw4 + 255) / 256, 256>>>(Wv, wvh, wvl, nw4);
    split_fp32<<<(nw4 + 255) / 256, 256>>>(Wo, woh, wol, nw4);

    dim3 gg(D / BN, MTOK / BM);   // (8, 64)
    gemm_mma<1><<<gg, 256, GEMM_SMEM>>>(xh, xl, wqh, wql, nullptr,
                                        nullptr, qh, ql);
    gemm_mma<1><<<gg, 256, GEMM_SMEM>>>(xh, xl, wkh, wkl, nullptr,
                                        nullptr, kh, kl);
    gemm_mma<1><<<gg, 256, GEMM_SMEM>>>(xh, xl, wvh, wvl, nullptr,
                                        nullptr, vh, vl);

    attn_mma<<<dim3(T / 128, H, B), 256, ATT_SMEM>>>(qh, ql, kh, kl, vh, vl,
                                                     aoh, aol);

    gemm_mma<0><<<gg, 256, GEMM_SMEM>>>(aoh, aol, woh, wol, bo,
                                        out, nullptr, nullptr);
}

// round 4
// speedup vs baseline: 2.8613x; 1.0997x over previous
#include <cuda_runtime.h>
#include <cuda_bf16.h>
#include <cstdint>

// ===========================================================================
// Problem constants
// ===========================================================================
constexpr int B = 4;
constexpr int T = 2048;
constexpr int D = 1024;
constexpr int H = 16;
constexpr int MTOK = B * T;          // 8192 token rows
using bf16 = __nv_bfloat16;

// ===========================================================================
// Scratch (allocation-free: __device__ globals), all bf16 hi/lo split pairs
// ===========================================================================
__device__ bf16 g_xh[(size_t)MTOK * D],  g_xl[(size_t)MTOK * D];
__device__ bf16 g_qh[(size_t)MTOK * D],  g_ql[(size_t)MTOK * D];
__device__ bf16 g_kh[(size_t)MTOK * D],  g_kl[(size_t)MTOK * D];
__device__ bf16 g_vh[(size_t)MTOK * D],  g_vl[(size_t)MTOK * D];
__device__ bf16 g_aoh[(size_t)MTOK * D], g_aol[(size_t)MTOK * D];
__device__ bf16 g_wqh[(size_t)D * D], g_wql[(size_t)D * D];
__device__ bf16 g_wkh[(size_t)D * D], g_wkl[(size_t)D * D];
__device__ bf16 g_wvh[(size_t)D * D], g_wvl[(size_t)D * D];
__device__ bf16 g_woh[(size_t)D * D], g_wol[(size_t)D * D];

// ===========================================================================
// PTX helpers (all sm_80-compatible; NO tcgen05 — compute_100 PTX target)
// ===========================================================================
__device__ __forceinline__ uint32_t cvta_smem(const void* p) {
    uint32_t a;
    asm("{ .reg .u64 t; cvta.to.shared.u64 t, %1; cvt.u32.u64 %0, t; }"
        : "=r"(a) : "l"(p));
    return a;
}

__device__ __forceinline__ void cp16(uint32_t dst, const void* src) {
    asm volatile("cp.async.cg.shared.global [%0], [%1], 16;"
                 :: "r"(dst), "l"(src));
}
#define CP_COMMIT() asm volatile("cp.async.commit_group;" ::: "memory")
template <int N>
__device__ __forceinline__ void cp_wait() {
    asm volatile("cp.async.wait_group %0;" :: "n"(N) : "memory");
}

__device__ __forceinline__ void ldm4(uint32_t* r, uint32_t a) {
    asm volatile("ldmatrix.sync.aligned.m8n8.x4.shared.b16 {%0,%1,%2,%3}, [%4];"
                 : "=r"(r[0]), "=r"(r[1]), "=r"(r[2]), "=r"(r[3]) : "r"(a));
}
__device__ __forceinline__ void ldm4t(uint32_t* r, uint32_t a) {
    asm volatile("ldmatrix.sync.aligned.m8n8.x4.trans.shared.b16 {%0,%1,%2,%3}, [%4];"
                 : "=r"(r[0]), "=r"(r[1]), "=r"(r[2]), "=r"(r[3]) : "r"(a));
}

__device__ __forceinline__ void mma_bf16(float* c, const uint32_t* a,
                                         const uint32_t* b) {
    asm volatile(
        "mma.sync.aligned.m16n8k16.row.col.f32.bf16.bf16.f32 "
        "{%0,%1,%2,%3}, {%4,%5,%6,%7}, {%8,%9}, {%0,%1,%2,%3};"
        : "+f"(c[0]), "+f"(c[1]), "+f"(c[2]), "+f"(c[3])
        : "r"(a[0]), "r"(a[1]), "r"(a[2]), "r"(a[3]), "r"(b[0]), "r"(b[1]));
}

__device__ __forceinline__ float ex2f(float x) {
    float r;
    asm("ex2.approx.f32 %0, %1;" : "=f"(r) : "f"(x));
    return r;
}

// split a pair of fp32 into packed bf16 hi and bf16 lo registers
__device__ __forceinline__ void split2(float v0, float v1,
                                       uint32_t& hp, uint32_t& lp) {
    bf16 h0 = __float2bfloat16(v0);
    bf16 h1 = __float2bfloat16(v1);
    bf16 l0 = __float2bfloat16(v0 - __bfloat162float(h0));
    bf16 l1 = __float2bfloat16(v1 - __bfloat162float(h1));
    hp = ((uint32_t)__bfloat16_as_ushort(h1) << 16) | __bfloat16_as_ushort(h0);
    lp = ((uint32_t)__bfloat16_as_ushort(l1) << 16) | __bfloat16_as_ushort(l0);
}

__device__ __forceinline__ void store_split2(bf16* Hh, bf16* Hl, size_t idx,
                                             float v0, float v1) {
    uint32_t hp, lp;
    split2(v0, v1, hp, lp);
    *(uint32_t*)(Hh + idx) = hp;
    *(uint32_t*)(Hl + idx) = lp;
}

// ===========================================================================
// fp32 -> (bf16 hi, bf16 lo) split
// ===========================================================================
__global__ void __launch_bounds__(256) split_fp32(const float* __restrict__ in,
                                                  bf16* __restrict__ hi,
                                                  bf16* __restrict__ lo,
                                                  int n4) {
    int i = blockIdx.x * 256 + threadIdx.x;
    if (i >= n4) return;
    int idx = i << 2;
    float4 v = *(const float4*)(in + idx);
    store_split2(hi, lo, idx,     v.x, v.y);
    store_split2(hi, lo, idx + 2, v.z, v.w);
}

// ===========================================================================
// mma.sync split-bf16 GEMM: C[M,N] = A[M,K] * Bw[N,K]^T (+bias)
// A = Ah+Al, B = Bh+Bl; C = Ah*Bh + Ah*Bl + Al*Bh (fp32 mma accum).
// Fixed: N = K = 1024. Tile 128x128, BK = 32, 8 warps of 64x32.
// Inner loop issues 3 passes of 16 INDEPENDENT mmas (RAW reuse distance 16).
// ===========================================================================
constexpr int BM = 128, BN = 128, BK = 32;
constexpr int KPADB = 80;                       // bytes per smem row (40 elems)
constexpr int ATILE = BM * KPADB;               // 10240
constexpr int STAGE = 4 * ATILE;                // 40960
constexpr int GEMM_SMEM = 2 * STAGE;            // 81920
constexpr int NC = D / BK;                      // 32

template <int OUT_BF16>
__global__ void __launch_bounds__(256) gemm_mma(
    const bf16* __restrict__ Ah, const bf16* __restrict__ Al,
    const bf16* __restrict__ Bh, const bf16* __restrict__ Bl,
    const float* __restrict__ bias,
    float* __restrict__ Cf, bf16* __restrict__ Ch, bf16* __restrict__ Cl)
{
    extern __shared__ __align__(16) char smraw[];
    const uint32_t sb0 = cvta_smem(smraw);
    const int tid = threadIdx.x, lane = tid & 31, w = tid >> 5;
    const int wm = w >> 2, wn = w & 3;
    const int bm = blockIdx.y * BM, bn = blockIdx.x * BN;
    const int g = lane >> 3, tr = lane & 7;

    const char* pAh = (const char*)Ah;
    const char* pAl = (const char*)Al;
    const char* pBh = (const char*)Bh;
    const char* pBl = (const char*)Bl;

    auto stage_load = [&](int c, int st) {
        const uint32_t sbs = sb0 + st * STAGE;
        const size_t koff = (size_t)c * (BK * 2);
#pragma unroll
        for (int i = 0; i < 2; i++) {
            int cid = tid + 256 * i;
            int r = cid >> 2, cc = cid & 3;
            uint32_t so = r * KPADB + cc * 16;
            size_t ga = (size_t)(bm + r) * 2048 + koff + cc * 16;
            size_t gb = (size_t)(bn + r) * 2048 + koff + cc * 16;
            cp16(sbs + so,             pAh + ga);
            cp16(sbs + ATILE + so,     pAl + ga);
            cp16(sbs + 2 * ATILE + so, pBh + gb);
            cp16(sbs + 3 * ATILE + so, pBl + gb);
        }
        CP_COMMIT();
    };

    float acc[4][4][4];
#pragma unroll
    for (int i = 0; i < 4; i++)
#pragma unroll
        for (int j = 0; j < 4; j++)
#pragma unroll
            for (int e = 0; e < 4; e++) acc[i][j][e] = 0.f;

    stage_load(0, 0);

    for (int c = 0; c < NC; c++) {
        const int st = c & 1;
        if (c + 1 < NC) { stage_load(c + 1, st ^ 1); cp_wait<1>(); }
        else            { cp_wait<0>(); }
        __syncthreads();
        const uint32_t sA = sb0 + st * STAGE;
        const uint32_t sB = sA + 2 * ATILE;
#pragma unroll
        for (int ks = 0; ks < 2; ks++) {
            uint32_t a[4][4], bh[2][4], bl[2][4];
            const uint32_t acol = (ks * 16 + (g >> 1) * 8) * 2;
            const uint32_t arow = (uint32_t)((g & 1) * 8 + tr);
            const uint32_t bcol = (ks * 16 + (g & 1) * 8) * 2;
            const uint32_t brow = (uint32_t)((g >> 1) * 8 + tr);
            // Load Ah + both B splits up front
#pragma unroll
            for (int mi = 0; mi < 4; mi++)
                ldm4(a[mi], sA + (wm * 64 + mi * 16 + arow) * KPADB + acol);
#pragma unroll
            for (int nh = 0; nh < 2; nh++) {
                uint32_t bd = sB + (wn * 32 + nh * 16 + brow) * KPADB + bcol;
                ldm4(bh[nh], bd);
                ldm4(bl[nh], bd + ATILE);
            }
            // Pass 1: Ah*Bh — 16 independent accumulators
#pragma unroll
            for (int mi = 0; mi < 4; mi++)
#pragma unroll
                for (int ni = 0; ni < 4; ni++)
                    mma_bf16(acc[mi][ni], a[mi], &bh[ni >> 1][(ni & 1) * 2]);
            // Pass 2: Ah*Bl
#pragma unroll
            for (int mi = 0; mi < 4; mi++)
#pragma unroll
                for (int ni = 0; ni < 4; ni++)
                    mma_bf16(acc[mi][ni], a[mi], &bl[ni >> 1][(ni & 1) * 2]);
            // Reload A <- Al, Pass 3: Al*Bh
#pragma unroll
            for (int mi = 0; mi < 4; mi++)
                ldm4(a[mi], sA + ATILE + (wm * 64 + mi * 16 + arow) * KPADB + acol);
#pragma unroll
            for (int mi = 0; mi < 4; mi++)
#pragma unroll
                for (int ni = 0; ni < 4; ni++)
                    mma_bf16(acc[mi][ni], a[mi], &bh[ni >> 1][(ni & 1) * 2]);
        }
        __syncthreads();
    }

    // Epilogue
    const int r0 = lane >> 2, c0 = (lane & 3) * 2;
#pragma unroll
    for (int mi = 0; mi < 4; mi++) {
        const int gr = bm + wm * 64 + mi * 16 + r0;
#pragma unroll
        for (int ni = 0; ni < 4; ni++) {
            const int gc = bn + wn * 32 + ni * 8 + c0;
            float v0 = acc[mi][ni][0], v1 = acc[mi][ni][1];
            float v2 = acc[mi][ni][2], v3 = acc[mi][ni][3];
            if (OUT_BF16) {
                store_split2(Ch, Cl, (size_t)gr * D + gc, v0, v1);
                store_split2(Ch, Cl, (size_t)(gr + 8) * D + gc, v2, v3);
            } else {
                float2 r4a = make_float2(v0 + bias[gc], v1 + bias[gc + 1]);
                float2 r4b = make_float2(v2 + bias[gc], v3 + bias[gc + 1]);
                *(float2*)(Cf + (size_t)gr * D + gc) = r4a;
                *(float2*)(Cf + (size_t)(gr + 8) * D + gc) = r4b;
            }
        }
    }
}

// ===========================================================================
// Flash attention (causal) with mma.sync split-bf16.
// CTA: 128 queries x 1 head. 8 warps x 16 query rows. KV streamed 64/step,
// double-buffered cp.async. P stays in registers. All mma passes are 8-wide
// independent (accumulator reuse distance 8).
// ===========================================================================
constexpr int APADB = 144;                       // 72 elems per smem row
constexpr int QTILE = 128 * APADB;               // 18432
constexpr int KTILE = 64 * APADB;                // 9216
constexpr int KVSTAGE = 4 * KTILE;               // 36864
constexpr int ATT_SMEM = 2 * QTILE + 2 * KVSTAGE;  // 110592

__global__ void __launch_bounds__(256) attn_mma(
    const bf16* __restrict__ Qh, const bf16* __restrict__ Ql,
    const bf16* __restrict__ Kh, const bf16* __restrict__ Kl,
    const bf16* __restrict__ Vh, const bf16* __restrict__ Vl,
    bf16* __restrict__ AOh, bf16* __restrict__ AOl)
{
    extern __shared__ __align__(16) char smraw[];
    const uint32_t sb = cvta_smem(smraw);
    const uint32_t sQ = sb;
    const int qt = blockIdx.x, h = blockIdx.y, b = blockIdx.z;
    const int tid = threadIdx.x, lane = tid & 31, w = tid >> 5;
    const int g = lane >> 3, tr = lane & 7;
    const size_t tok0 = (size_t)(b * T + qt * 128);
    const size_t hoff = (size_t)h * 128;        // byte col offset of head

#pragma unroll
    for (int i = 0; i < 4; i++) {
        int cid = tid + 256 * i;
        int r = cid >> 3, cc = cid & 7;
        uint32_t so = r * APADB + cc * 16;
        size_t go = (tok0 + r) * 2048 + hoff + cc * 16;
        cp16(sQ + so,         (const char*)Qh + go);
        cp16(sQ + QTILE + so, (const char*)Ql + go);
    }
    auto kv_load = [&](int j, int st) {
        uint32_t skv = sb + 2 * QTILE + st * KVSTAGE;
        size_t kt0 = (size_t)(b * T + j * 64);
#pragma unroll
        for (int i = 0; i < 2; i++) {
            int cid = tid + 256 * i;
            int r = cid >> 3, cc = cid & 7;
            uint32_t so = r * APADB + cc * 16;
            size_t go = (kt0 + r) * 2048 + hoff + cc * 16;
            cp16(skv + so,             (const char*)Kh + go);
            cp16(skv + KTILE + so,     (const char*)Kl + go);
            cp16(skv + 2 * KTILE + so, (const char*)Vh + go);
            cp16(skv + 3 * KTILE + so, (const char*)Vl + go);
        }
        CP_COMMIT();
    };
    kv_load(0, 0);

    float accO[8][4];
#pragma unroll
    for (int f = 0; f < 8; f++)
#pragma unroll
        for (int e = 0; e < 4; e++) accO[f][e] = 0.f;
    float m0 = -1e30f, m1 = -1e30f, l0 = 0.f, l1 = 0.f;

    const int jmax = 2 * qt + 1;
    const int qg0 = qt * 128 + w * 16 + (lane >> 2);
    const float SCALE = 0.125f;
    const float L2E = 1.4426950408889634f;

    for (int j = 0; j <= jmax; j++) {
        const int st = j & 1;
        if (j < jmax) { kv_load(j + 1, st ^ 1); cp_wait<1>(); }
        else          { cp_wait<0>(); }
        __syncthreads();
        const uint32_t sK = sb + 2 * QTILE + st * KVSTAGE;
        const uint32_t sV = sK + 2 * KTILE;

        // ---- S = Q K^T (3-term split, 8-wide independent passes) ----
        float s[8][4];
#pragma unroll
        for (int f = 0; f < 8; f++)
#pragma unroll
            for (int e = 0; e < 4; e++) s[f][e] = 0.f;

        const uint32_t qrow = (uint32_t)(w * 16 + (g & 1) * 8 + tr);
        const uint32_t brow = (uint32_t)((g >> 1) * 8 + tr);
#pragma unroll
        for (int ks = 0; ks < 4; ks++) {
            uint32_t qh[4], ql[4], kf[4][4];
            uint32_t qaddr = sQ + qrow * APADB + (ks * 16 + (g >> 1) * 8) * 2;
            ldm4(qh, qaddr);
            ldm4(ql, qaddr + QTILE);
            const uint32_t bcol = (ks * 16 + (g & 1) * 8) * 2;
#pragma unroll
            for (int nh = 0; nh < 4; nh++)
                ldm4(kf[nh], sK + (nh * 16 + brow) * APADB + bcol);
            // Pass 1: Qh*Kh (8 independent)
#pragma unroll
            for (int nh = 0; nh < 4; nh++) {
                mma_bf16(s[2 * nh],     qh, kf[nh]);
                mma_bf16(s[2 * nh + 1], qh, kf[nh] + 2);
            }
            // Pass 2: Ql*Kh
#pragma unroll
            for (int nh = 0; nh < 4; nh++) {
                mma_bf16(s[2 * nh],     ql, kf[nh]);
                mma_bf16(s[2 * nh + 1], ql, kf[nh] + 2);
            }
            // Reload K <- Kl, Pass 3: Qh*Kl
#pragma unroll
            for (int nh = 0; nh < 4; nh++)
                ldm4(kf[nh], sK + KTILE + (nh * 16 + brow) * APADB + bcol);
#pragma unroll
            for (int nh = 0; nh < 4; nh++) {
                mma_bf16(s[2 * nh],     qh, kf[nh]);
                mma_bf16(s[2 * nh + 1], qh, kf[nh] + 2);
            }
        }

        // ---- scale + causal mask ----
        const bool need_mask = (j >= 2 * qt);
#pragma unroll
        for (int f = 0; f < 8; f++) {
            const int kgb = j * 64 + f * 8 + (lane & 3) * 2;
#pragma unroll
            for (int e = 0; e < 4; e++) {
                const int kg = kgb + (e & 1);
                const int qg = qg0 + (e >> 1) * 8;
                float v = s[f][e] * SCALE;
                if (need_mask && kg > qg) v = -1e30f;
                s[f][e] = v;
            }
        }

        // ---- online softmax (quad-wide reductions) ----
        float mx0 = -1e30f, mx1 = -1e30f;
#pragma unroll
        for (int f = 0; f < 8; f++) {
            mx0 = fmaxf(mx0, fmaxf(s[f][0], s[f][1]));
            mx1 = fmaxf(mx1, fmaxf(s[f][2], s[f][3]));
        }
        mx0 = fmaxf(mx0, __shfl_xor_sync(0xffffffffu, mx0, 1));
        mx0 = fmaxf(mx0, __shfl_xor_sync(0xffffffffu, mx0, 2));
        mx1 = fmaxf(mx1, __shfl_xor_sync(0xffffffffu, mx1, 1));
        mx1 = fmaxf(mx1, __shfl_xor_sync(0xffffffffu, mx1, 2));
        const float mn0 = fmaxf(m0, mx0);
        const float mn1 = fmaxf(m1, mx1);
        const float cr0 = ex2f((m0 - mn0) * L2E);
        const float cr1 = ex2f((m1 - mn1) * L2E);
        float sum0 = 0.f, sum1 = 0.f;
#pragma unroll
        for (int f = 0; f < 8; f++) {
            float p0 = ex2f((s[f][0] - mn0) * L2E);
            float p1 = ex2f((s[f][1] - mn0) * L2E);
            float p2 = ex2f((s[f][2] - mn1) * L2E);
            float p3 = ex2f((s[f][3] - mn1) * L2E);
            s[f][0] = p0; s[f][1] = p1; s[f][2] = p2; s[f][3] = p3;
            sum0 += p0 + p1;
            sum1 += p2 + p3;
        }
        sum0 += __shfl_xor_sync(0xffffffffu, sum0, 1);
        sum0 += __shfl_xor_sync(0xffffffffu, sum0, 2);
        sum1 += __shfl_xor_sync(0xffffffffu, sum1, 1);
        sum1 += __shfl_xor_sync(0xffffffffu, sum1, 2);
        l0 = l0 * cr0 + sum0;
        l1 = l1 * cr1 + sum1;
        m0 = mn0; m1 = mn1;
#pragma unroll
        for (int f = 0; f < 8; f++) {
            accO[f][0] *= cr0; accO[f][1] *= cr0;
            accO[f][2] *= cr1; accO[f][3] *= cr1;
        }

        // ---- O += P V (P from registers, 8-wide independent passes) ----
#pragma unroll
        for (int k2 = 0; k2 < 4; k2++) {
            uint32_t afh[4], afl[4], vf[4][4];
            split2(s[2 * k2][0],     s[2 * k2][1],     afh[0], afl[0]);
            split2(s[2 * k2][2],     s[2 * k2][3],     afh[1], afl[1]);
            split2(s[2 * k2 + 1][0], s[2 * k2 + 1][1], afh[2], afl[2]);
            split2(s[2 * k2 + 1][2], s[2 * k2 + 1][3], afh[3], afl[3]);
            const uint32_t vrow = (uint32_t)(k2 * 16 + (g & 1) * 8 + tr);
#pragma unroll
            for (int db = 0; db < 4; db++)
                ldm4t(vf[db], sV + vrow * APADB + (db * 16 + (g >> 1) * 8) * 2);
            // Pass 1: Ph*Vh (8 independent)
#pragma unroll
            for (int db = 0; db < 4; db++) {
                mma_bf16(accO[2 * db],     afh, vf[db]);
                mma_bf16(accO[2 * db + 1], afh, vf[db] + 2);
            }
            // Pass 2: Pl*Vh
#pragma unroll
            for (int db = 0; db < 4; db++) {
                mma_bf16(accO[2 * db],     afl, vf[db]);
                mma_bf16(accO[2 * db + 1], afl, vf[db] + 2);
            }
            // Reload V <- Vl, Pass 3: Ph*Vl
#pragma unroll
            for (int db = 0; db < 4; db++)
                ldm4t(vf[db], sV + KTILE + vrow * APADB + (db * 16 + (g >> 1) * 8) * 2);
#pragma unroll
            for (int db = 0; db < 4; db++) {
                mma_bf16(accO[2 * db],     afh, vf[db]);
                mma_bf16(accO[2 * db + 1], afh, vf[db] + 2);
            }
        }
        __syncthreads();   // protect KV stage before next prefetch overwrites
    }

    // ---- epilogue: normalize, bf16-split store ----
    const float inv0 = 1.f / l0;
    const float inv1 = 1.f / l1;
    const size_t r0g = tok0 + w * 16 + (lane >> 2);
    const int c0 = (lane & 3) * 2;
#pragma unroll
    for (int f = 0; f < 8; f++) {
        const int gc = h * 64 + f * 8 + c0;
        store_split2(AOh, AOl, r0g * D + gc,
                     accO[f][0] * inv0, accO[f][1] * inv0);
        store_split2(AOh, AOl, (r0g + 8) * D + gc,
                     accO[f][2] * inv1, accO[f][3] * inv1);
    }
}

// ===========================================================================
extern "C" void kernel_launch(void* const* d_in, const int* in_sizes, int n_in,
                              void* d_out, int out_size)
{
    (void)in_sizes; (void)n_in; (void)out_size;
    const float* x  = (const float*)d_in[0];
    const float* Wq = (const float*)d_in[1];
    const float* Wk = (const float*)d_in[2];
    const float* Wv = (const float*)d_in[3];
    const float* Wo = (const float*)d_in[4];
    const float* bo = (const float*)d_in[5];
    float* out = (float*)d_out;

    bf16 *xh, *xl, *qh, *ql, *kh, *kl, *vh, *vl, *aoh, *aol;
    bf16 *wqh, *wql, *wkh, *wkl, *wvh, *wvl, *woh, *wol;
    cudaGetSymbolAddress((void**)&xh,  g_xh);
    cudaGetSymbolAddress((void**)&xl,  g_xl);
    cudaGetSymbolAddress((void**)&qh,  g_qh);
    cudaGetSymbolAddress((void**)&ql,  g_ql);
    cudaGetSymbolAddress((void**)&kh,  g_kh);
    cudaGetSymbolAddress((void**)&kl,  g_kl);
    cudaGetSymbolAddress((void**)&vh,  g_vh);
    cudaGetSymbolAddress((void**)&vl,  g_vl);
    cudaGetSymbolAddress((void**)&aoh, g_aoh);
    cudaGetSymbolAddress((void**)&aol, g_aol);
    cudaGetSymbolAddress((void**)&wqh, g_wqh);
    cudaGetSymbolAddress((void**)&wql, g_wql);
    cudaGetSymbolAddress((void**)&wkh, g_wkh);
    cudaGetSymbolAddress((void**)&wkl, g_wkl);
    cudaGetSymbolAddress((void**)&wvh, g_wvh);
    cudaGetSymbolAddress((void**)&wvl, g_wvl);
    cudaGetSymbolAddress((void**)&woh, g_woh);
    cudaGetSymbolAddress((void**)&wol, g_wol);

    cudaFuncSetAttribute(gemm_mma<1>, cudaFuncAttributeMaxDynamicSharedMemorySize,
                         GEMM_SMEM);
    cudaFuncSetAttribute(gemm_mma<0>, cudaFuncAttributeMaxDynamicSharedMemorySize,
                         GEMM_SMEM);
    cudaFuncSetAttribute(attn_mma, cudaFuncAttributeMaxDynamicSharedMemorySize,
                         ATT_SMEM);

    const int nx4 = MTOK * D / 4;
    const int nw4 = D * D / 4;
    split_fp32<<<(nx4 + 255) / 256, 256>>>(x,  xh,  xl,  nx4);
    split_fp32<<<(nw4 + 255) / 256, 256>>>(Wq, wqh, wql, nw4);
    split_fp32<<<(nw4 + 255) / 256, 256>>>(Wk, wkh, wkl, nw4);
    split_fp32<<<(nw4 + 255) / 256, 256>>>(Wv, wvh, wvl, nw4);
    split_fp32<<<(nw4 + 255) / 256, 256>>>(Wo, woh, wol, nw4);

    dim3 gg(D / BN, MTOK / BM);   // (8, 64)
    gemm_mma<1><<<gg, 256, GEMM_SMEM>>>(xh, xl, wqh, wql, nullptr,
                                        nullptr, qh, ql);
    gemm_mma<1><<<gg, 256, GEMM_SMEM>>>(xh, xl, wkh, wkl, nullptr,
                                        nullptr, kh, kl);
    gemm_mma<1><<<gg, 256, GEMM_SMEM>>>(xh, xl, wvh, wvl, nullptr,
                                        nullptr, vh, vl);

    attn_mma<<<dim3(T / 128, H, B), 256, ATT_SMEM>>>(qh, ql, kh, kl, vh, vl,
                                                     aoh, aol);

    gemm_mma<0><<<gg, 256, GEMM_SMEM>>>(aoh, aol, woh, wol, bo,
                                        out, nullptr, nullptr);
}

// round 7
// speedup vs baseline: 3.8552x; 1.3474x over previous
#include <cuda_runtime.h>
#include <cuda_fp16.h>
#include <cstdint>

// ===========================================================================
// Problem constants
// ===========================================================================
constexpr int B = 4;
constexpr int T = 2048;
constexpr int D = 1024;
constexpr int H = 16;
constexpr int MTOK = B * T;          // 8192 token rows
using f16 = __half;

// ===========================================================================
// Scratch (allocation-free: __device__ globals)
// fp16 2-term scheme: left operands keep (hi, lo); right operands hi only.
// ===========================================================================
__device__ f16 g_xh[(size_t)MTOK * D],  g_xl[(size_t)MTOK * D];
__device__ f16 g_qh[(size_t)MTOK * D],  g_ql[(size_t)MTOK * D];
__device__ f16 g_kh[(size_t)MTOK * D];
__device__ f16 g_vh[(size_t)MTOK * D];
__device__ f16 g_aoh[(size_t)MTOK * D], g_aol[(size_t)MTOK * D];
__device__ f16 g_wqh[(size_t)D * D];
__device__ f16 g_wkh[(size_t)D * D];
__device__ f16 g_wvh[(size_t)D * D];
__device__ f16 g_woh[(size_t)D * D];

// ===========================================================================
// PTX helpers (sm_80-compatible; compute_100 PTX target — no tcgen05)
// ===========================================================================
__device__ __forceinline__ uint32_t cvta_smem(const void* p) {
    uint32_t a;
    asm("{ .reg .u64 t; cvta.to.shared.u64 t, %1; cvt.u32.u64 %0, t; }"
        : "=r"(a) : "l"(p));
    return a;
}

__device__ __forceinline__ void cp16(uint32_t dst, const void* src) {
    asm volatile("cp.async.cg.shared.global [%0], [%1], 16;"
                 :: "r"(dst), "l"(src));
}
#define CP_COMMIT() asm volatile("cp.async.commit_group;" ::: "memory")
template <int N>
__device__ __forceinline__ void cp_wait() {
    asm volatile("cp.async.wait_group %0;" :: "n"(N) : "memory");
}

__device__ __forceinline__ void ldm4(uint32_t* r, uint32_t a) {
    asm volatile("ldmatrix.sync.aligned.m8n8.x4.shared.b16 {%0,%1,%2,%3}, [%4];"
                 : "=r"(r[0]), "=r"(r[1]), "=r"(r[2]), "=r"(r[3]) : "r"(a));
}
__device__ __forceinline__ void ldm4t(uint32_t* r, uint32_t a) {
    asm volatile("ldmatrix.sync.aligned.m8n8.x4.trans.shared.b16 {%0,%1,%2,%3}, [%4];"
                 : "=r"(r[0]), "=r"(r[1]), "=r"(r[2]), "=r"(r[3]) : "r"(a));
}

__device__ __forceinline__ void mma_f16(float* c, const uint32_t* a,
                                        const uint32_t* b) {
    asm volatile(
        "mma.sync.aligned.m16n8k16.row.col.f32.f16.f16.f32 "
        "{%0,%1,%2,%3}, {%4,%5,%6,%7}, {%8,%9}, {%0,%1,%2,%3};"
        : "+f"(c[0]), "+f"(c[1]), "+f"(c[2]), "+f"(c[3])
        : "r"(a[0]), "r"(a[1]), "r"(a[2]), "r"(a[3]), "r"(b[0]), "r"(b[1]));
}

__device__ __forceinline__ float ex2f(float x) {
    float r;
    asm("ex2.approx.f32 %0, %1;" : "=f"(r) : "f"(x));
    return r;
}

// split a pair of fp32 into packed fp16 hi and fp16 lo registers
__device__ __forceinline__ void split2(float v0, float v1,
                                       uint32_t& hp, uint32_t& lp) {
    f16 h0 = __float2half_rn(v0);
    f16 h1 = __float2half_rn(v1);
    f16 l0 = __float2half_rn(v0 - __half2float(h0));
    f16 l1 = __float2half_rn(v1 - __half2float(h1));
    hp = ((uint32_t)__half_as_ushort(h1) << 16) | __half_as_ushort(h0);
    lp = ((uint32_t)__half_as_ushort(l1) << 16) | __half_as_ushort(l0);
}

__device__ __forceinline__ void store_split2(f16* Hh, f16* Hl, size_t idx,
                                             float v0, float v1) {
    uint32_t hp, lp;
    split2(v0, v1, hp, lp);
    *(uint32_t*)(Hh + idx) = hp;
    *(uint32_t*)(Hl + idx) = lp;
}

// ===========================================================================
// fp32 -> (fp16 hi, fp16 lo) split, and fp32 -> fp16 convert (weights)
// ===========================================================================
__global__ void __launch_bounds__(256) split_hl(const float* __restrict__ in,
                                                f16* __restrict__ hi,
                                                f16* __restrict__ lo, int n4) {
    int i = blockIdx.x * 256 + threadIdx.x;
    if (i >= n4) return;
    int idx = i << 2;
    float4 v = *(const float4*)(in + idx);
    store_split2(hi, lo, idx,     v.x, v.y);
    store_split2(hi, lo, idx + 2, v.z, v.w);
}

__global__ void __launch_bounds__(256) conv_h(const float* __restrict__ in,
                                              f16* __restrict__ hi, int n4) {
    int i = blockIdx.x * 256 + threadIdx.x;
    if (i >= n4) return;
    int idx = i << 2;
    float4 v = *(const float4*)(in + idx);
    uint32_t p0 = ((uint32_t)__half_as_ushort(__float2half_rn(v.y)) << 16) |
                  __half_as_ushort(__float2half_rn(v.x));
    uint32_t p1 = ((uint32_t)__half_as_ushort(__float2half_rn(v.w)) << 16) |
                  __half_as_ushort(__float2half_rn(v.z));
    *(uint32_t*)(hi + idx)     = p0;
    *(uint32_t*)(hi + idx + 2) = p1;
}

// ===========================================================================
// mma.sync fp16 2-term GEMM: C[M,N] = A[M,K] * Bw[N,K]^T (+bias)
// A = Ah+Al fp16, B = Bh fp16; C = Ah*Bh + Al*Bh (fp32 mma accum).
// Fixed: N = K = 1024. Tile 128x128, BK = 32, 8 warps of 64x32.
// OUT_MODE: 0 = fp32 + bias, 1 = fp16 hi+lo split, 2 = fp16 hi only.
// ===========================================================================
constexpr int BM = 128, BN = 128, BK = 32;
constexpr int KPADB = 80;                       // bytes per smem row (40 elems)
constexpr int ATILE = BM * KPADB;               // 10240
constexpr int STAGE = 3 * ATILE;                // Ah, Al, Bh = 30720
constexpr int GEMM_SMEM = 2 * STAGE;            // 61440
constexpr int NC = D / BK;                      // 32

template <int OUT_MODE>
__global__ void __launch_bounds__(256) gemm_mma(
    const f16* __restrict__ Ah, const f16* __restrict__ Al,
    const f16* __restrict__ Bh,
    const float* __restrict__ bias,
    float* __restrict__ Cf, f16* __restrict__ Ch, f16* __restrict__ Cl)
{
    extern __shared__ __align__(16) char smraw[];
    const uint32_t sb0 = cvta_smem(smraw);
    const int tid = threadIdx.x, lane = tid & 31, w = tid >> 5;
    const int wm = w >> 2, wn = w & 3;
    const int bm = blockIdx.y * BM, bn = blockIdx.x * BN;
    const int g = lane >> 3, tr = lane & 7;

    const char* pAh = (const char*)Ah;
    const char* pAl = (const char*)Al;
    const char* pBh = (const char*)Bh;

    auto stage_load = [&](int c, int st) {
        const uint32_t sbs = sb0 + st * STAGE;
        const size_t koff = (size_t)c * (BK * 2);
#pragma unroll
        for (int i = 0; i < 2; i++) {
            int cid = tid + 256 * i;
            int r = cid >> 2, cc = cid & 3;
            uint32_t so = r * KPADB + cc * 16;
            size_t ga = (size_t)(bm + r) * 2048 + koff + cc * 16;
            size_t gb = (size_t)(bn + r) * 2048 + koff + cc * 16;
            cp16(sbs + so,             pAh + ga);
            cp16(sbs + ATILE + so,     pAl + ga);
            cp16(sbs + 2 * ATILE + so, pBh + gb);
        }
        CP_COMMIT();
    };

    float acc[4][4][4];
#pragma unroll
    for (int i = 0; i < 4; i++)
#pragma unroll
        for (int j = 0; j < 4; j++)
#pragma unroll
            for (int e = 0; e < 4; e++) acc[i][j][e] = 0.f;

    stage_load(0, 0);

    for (int c = 0; c < NC; c++) {
        const int st = c & 1;
        if (c + 1 < NC) { stage_load(c + 1, st ^ 1); cp_wait<1>(); }
        else            { cp_wait<0>(); }
        __syncthreads();
        const uint32_t sA = sb0 + st * STAGE;
        const uint32_t sB = sA + 2 * ATILE;
#pragma unroll
        for (int ks = 0; ks < 2; ks++) {
            uint32_t a[4][4], bh[2][4];
            const uint32_t acol = (ks * 16 + (g >> 1) * 8) * 2;
            const uint32_t arow = (uint32_t)((g & 1) * 8 + tr);
            const uint32_t bcol = (ks * 16 + (g & 1) * 8) * 2;
            const uint32_t brow = (uint32_t)((g >> 1) * 8 + tr);
#pragma unroll
            for (int mi = 0; mi < 4; mi++)
                ldm4(a[mi], sA + (wm * 64 + mi * 16 + arow) * KPADB + acol);
#pragma unroll
            for (int nh = 0; nh < 2; nh++)
                ldm4(bh[nh], sB + (wn * 32 + nh * 16 + brow) * KPADB + bcol);
            // Pass 1: Ah*Bh — 16 independent accumulators
#pragma unroll
            for (int mi = 0; mi < 4; mi++)
#pragma unroll
                for (int ni = 0; ni < 4; ni++)
                    mma_f16(acc[mi][ni], a[mi], &bh[ni >> 1][(ni & 1) * 2]);
            // Reload A <- Al, Pass 2: Al*Bh
#pragma unroll
            for (int mi = 0; mi < 4; mi++)
                ldm4(a[mi], sA + ATILE + (wm * 64 + mi * 16 + arow) * KPADB + acol);
#pragma unroll
            for (int mi = 0; mi < 4; mi++)
#pragma unroll
                for (int ni = 0; ni < 4; ni++)
                    mma_f16(acc[mi][ni], a[mi], &bh[ni >> 1][(ni & 1) * 2]);
        }
        __syncthreads();
    }

    // Epilogue
    const int r0 = lane >> 2, c0 = (lane & 3) * 2;
#pragma unroll
    for (int mi = 0; mi < 4; mi++) {
        const int gr = bm + wm * 64 + mi * 16 + r0;
#pragma unroll
        for (int ni = 0; ni < 4; ni++) {
            const int gc = bn + wn * 32 + ni * 8 + c0;
            float v0 = acc[mi][ni][0], v1 = acc[mi][ni][1];
            float v2 = acc[mi][ni][2], v3 = acc[mi][ni][3];
            if (OUT_MODE == 1) {
                store_split2(Ch, Cl, (size_t)gr * D + gc, v0, v1);
                store_split2(Ch, Cl, (size_t)(gr + 8) * D + gc, v2, v3);
            } else if (OUT_MODE == 2) {
                uint32_t hp, lp;
                split2(v0, v1, hp, lp);
                *(uint32_t*)(Ch + (size_t)gr * D + gc) = hp;
                split2(v2, v3, hp, lp);
                *(uint32_t*)(Ch + (size_t)(gr + 8) * D + gc) = hp;
            } else {
                float2 r4a = make_float2(v0 + bias[gc], v1 + bias[gc + 1]);
                float2 r4b = make_float2(v2 + bias[gc], v3 + bias[gc + 1]);
                *(float2*)(Cf + (size_t)gr * D + gc) = r4a;
                *(float2*)(Cf + (size_t)(gr + 8) * D + gc) = r4b;
            }
        }
    }
}

// ===========================================================================
// Flash attention (causal), fp16 2-term. CTA: 128 queries x 1 head, 8 warps
// x 16 query rows. KV streamed 64 keys/step (Kh + Vh only), double-buffered.
// S = (Qh+Ql)*Kh; O += (Ph+Pl)*Vh with P split in registers.
// ===========================================================================
constexpr int APADB = 144;                       // 72 elems per smem row
constexpr int QTILE = 128 * APADB;               // 18432
constexpr int KTILE = 64 * APADB;                // 9216
constexpr int KVSTAGE = 2 * KTILE;               // 18432 (Kh + Vh)
constexpr int ATT_SMEM = 2 * QTILE + 2 * KVSTAGE;  // 73728

__global__ void __launch_bounds__(256) attn_mma(
    const f16* __restrict__ Qh, const f16* __restrict__ Ql,
    const f16* __restrict__ Kh, const f16* __restrict__ Vh,
    f16* __restrict__ AOh, f16* __restrict__ AOl)
{
    extern __shared__ __align__(16) char smraw[];
    const uint32_t sb = cvta_smem(smraw);
    const uint32_t sQ = sb;
    const int qt = blockIdx.x, h = blockIdx.y, b = blockIdx.z;
    const int tid = threadIdx.x, lane = tid & 31, w = tid >> 5;
    const int g = lane >> 3, tr = lane & 7;
    const size_t tok0 = (size_t)(b * T + qt * 128);
    const size_t hoff = (size_t)h * 128;        // byte col offset of head

#pragma unroll
    for (int i = 0; i < 4; i++) {
        int cid = tid + 256 * i;
        int r = cid >> 3, cc = cid & 7;
        uint32_t so = r * APADB + cc * 16;
        size_t go = (tok0 + r) * 2048 + hoff + cc * 16;
        cp16(sQ + so,         (const char*)Qh + go);
        cp16(sQ + QTILE + so, (const char*)Ql + go);
    }
    auto kv_load = [&](int j, int st) {
        uint32_t skv = sb + 2 * QTILE + st * KVSTAGE;
        size_t kt0 = (size_t)(b * T + j * 64);
#pragma unroll
        for (int i = 0; i < 2; i++) {
            int cid = tid + 256 * i;
            int r = cid >> 3, cc = cid & 7;
            uint32_t so = r * APADB + cc * 16;
            size_t go = (kt0 + r) * 2048 + hoff + cc * 16;
            cp16(skv + so,         (const char*)Kh + go);
            cp16(skv + KTILE + so, (const char*)Vh + go);
        }
        CP_COMMIT();
    };
    kv_load(0, 0);

    float accO[8][4];
#pragma unroll
    for (int f = 0; f < 8; f++)
#pragma unroll
        for (int e = 0; e < 4; e++) accO[f][e] = 0.f;
    float m0 = -1e30f, m1 = -1e30f, l0 = 0.f, l1 = 0.f;

    const int jmax = 2 * qt + 1;
    const int qg0 = qt * 128 + w * 16 + (lane >> 2);
    const float SCALE = 0.125f;
    const float L2E = 1.4426950408889634f;

    for (int j = 0; j <= jmax; j++) {
        const int st = j & 1;
        if (j < jmax) { kv_load(j + 1, st ^ 1); cp_wait<1>(); }
        else          { cp_wait<0>(); }
        __syncthreads();
        const uint32_t sK = sb + 2 * QTILE + st * KVSTAGE;
        const uint32_t sV = sK + KTILE;

        // ---- S = (Qh+Ql) Kh^T (2 passes of 8 independent mmas) ----
        float s[8][4];
#pragma unroll
        for (int f = 0; f < 8; f++)
#pragma unroll
            for (int e = 0; e < 4; e++) s[f][e] = 0.f;

        const uint32_t qrow = (uint32_t)(w * 16 + (g & 1) * 8 + tr);
        const uint32_t brow = (uint32_t)((g >> 1) * 8 + tr);
#pragma unroll
        for (int ks = 0; ks < 4; ks++) {
            uint32_t qh[4], ql[4], kf[4][4];
            uint32_t qaddr = sQ + qrow * APADB + (ks * 16 + (g >> 1) * 8) * 2;
            ldm4(qh, qaddr);
            ldm4(ql, qaddr + QTILE);
            const uint32_t bcol = (ks * 16 + (g & 1) * 8) * 2;
#pragma unroll
            for (int nh = 0; nh < 4; nh++)
                ldm4(kf[nh], sK + (nh * 16 + brow) * APADB + bcol);
#pragma unroll
            for (int nh = 0; nh < 4; nh++) {
                mma_f16(s[2 * nh],     qh, kf[nh]);
                mma_f16(s[2 * nh + 1], qh, kf[nh] + 2);
            }
#pragma unroll
            for (int nh = 0; nh < 4; nh++) {
                mma_f16(s[2 * nh],     ql, kf[nh]);
                mma_f16(s[2 * nh + 1], ql, kf[nh] + 2);
            }
        }

        // ---- scale + causal mask ----
        const bool need_mask = (j >= 2 * qt);
#pragma unroll
        for (int f = 0; f < 8; f++) {
            const int kgb = j * 64 + f * 8 + (lane & 3) * 2;
#pragma unroll
            for (int e = 0; e < 4; e++) {
                const int kg = kgb + (e & 1);
                const int qg = qg0 + (e >> 1) * 8;
                float v = s[f][e] * SCALE;
                if (need_mask && kg > qg) v = -1e30f;
                s[f][e] = v;
            }
        }

        // ---- online softmax (quad-wide reductions) ----
        float mx0 = -1e30f, mx1 = -1e30f;
#pragma unroll
        for (int f = 0; f < 8; f++) {
            mx0 = fmaxf(mx0, fmaxf(s[f][0], s[f][1]));
            mx1 = fmaxf(mx1, fmaxf(s[f][2], s[f][3]));
        }
        mx0 = fmaxf(mx0, __shfl_xor_sync(0xffffffffu, mx0, 1));
        mx0 = fmaxf(mx0, __shfl_xor_sync(0xffffffffu, mx0, 2));
        mx1 = fmaxf(mx1, __shfl_xor_sync(0xffffffffu, mx1, 1));
        mx1 = fmaxf(mx1, __shfl_xor_sync(0xffffffffu, mx1, 2));
        const float mn0 = fmaxf(m0, mx0);
        const float mn1 = fmaxf(m1, mx1);
        const float cr0 = ex2f((m0 - mn0) * L2E);
        const float cr1 = ex2f((m1 - mn1) * L2E);
        float sum0 = 0.f, sum1 = 0.f;
#pragma unroll
        for (int f = 0; f < 8; f++) {
            float p0 = ex2f((s[f][0] - mn0) * L2E);
            float p1 = ex2f((s[f][1] - mn0) * L2E);
            float p2 = ex2f((s[f][2] - mn1) * L2E);
            float p3 = ex2f((s[f][3] - mn1) * L2E);
            s[f][0] = p0; s[f][1] = p1; s[f][2] = p2; s[f][3] = p3;
            sum0 += p0 + p1;
            sum1 += p2 + p3;
        }
        sum0 += __shfl_xor_sync(0xffffffffu, sum0, 1);
        sum0 += __shfl_xor_sync(0xffffffffu, sum0, 2);
        sum1 += __shfl_xor_sync(0xffffffffu, sum1, 1);
        sum1 += __shfl_xor_sync(0xffffffffu, sum1, 2);
        l0 = l0 * cr0 + sum0;
        l1 = l1 * cr1 + sum1;
        m0 = mn0; m1 = mn1;
#pragma unroll
        for (int f = 0; f < 8; f++) {
            accO[f][0] *= cr0; accO[f][1] *= cr0;
            accO[f][2] *= cr1; accO[f][3] *= cr1;
        }

        // ---- O += (Ph+Pl) Vh (P split in registers, 2 passes of 8) ----
#pragma unroll
        for (int k2 = 0; k2 < 4; k2++) {
            uint32_t afh[4], afl[4], vf[4][4];
            split2(s[2 * k2][0],     s[2 * k2][1],     afh[0], afl[0]);
            split2(s[2 * k2][2],     s[2 * k2][3],     afh[1], afl[1]);
            split2(s[2 * k2 + 1][0], s[2 * k2 + 1][1], afh[2], afl[2]);
            split2(s[2 * k2 + 1][2], s[2 * k2 + 1][3], afh[3], afl[3]);
            const uint32_t vrow = (uint32_t)(k2 * 16 + (g & 1) * 8 + tr);
#pragma unroll
            for (int db = 0; db < 4; db++)
                ldm4t(vf[db], sV + vrow * APADB + (db * 16 + (g >> 1) * 8) * 2);
#pragma unroll
            for (int db = 0; db < 4; db++) {
                mma_f16(accO[2 * db],     afh, vf[db]);
                mma_f16(accO[2 * db + 1], afh, vf[db] + 2);
            }
#pragma unroll
            for (int db = 0; db < 4; db++) {
                mma_f16(accO[2 * db],     afl, vf[db]);
                mma_f16(accO[2 * db + 1], afl, vf[db] + 2);
            }
        }
        __syncthreads();   // protect KV stage before next prefetch overwrites
    }

    // ---- epilogue: normalize, fp16-split store ----
    const float inv0 = 1.f / l0;
    const float inv1 = 1.f / l1;
    const size_t r0g = tok0 + w * 16 + (lane >> 2);
    const int c0 = (lane & 3) * 2;
#pragma unroll
    for (int f = 0; f < 8; f++) {
        const int gc = h * 64 + f * 8 + c0;
        store_split2(AOh, AOl, r0g * D + gc,
                     accO[f][0] * inv0, accO[f][1] * inv0);
        store_split2(AOh, AOl, (r0g + 8) * D + gc,
                     accO[f][2] * inv1, accO[f][3] * inv1);
    }
}

// ===========================================================================
extern "C" void kernel_launch(void* const* d_in, const int* in_sizes, int n_in,
                              void* d_out, int out_size)
{
    (void)in_sizes; (void)n_in; (void)out_size;
    const float* x  = (const float*)d_in[0];
    const float* Wq = (const float*)d_in[1];
    const float* Wk = (const float*)d_in[2];
    const float* Wv = (const float*)d_in[3];
    const float* Wo = (const float*)d_in[4];
    const float* bo = (const float*)d_in[5];
    float* out = (float*)d_out;

    f16 *xh, *xl, *qh, *ql, *kh, *vh, *aoh, *aol;
    f16 *wqh, *wkh, *wvh, *woh;
    cudaGetSymbolAddress((void**)&xh,  g_xh);
    cudaGetSymbolAddress((void**)&xl,  g_xl);
    cudaGetSymbolAddress((void**)&qh,  g_qh);
    cudaGetSymbolAddress((void**)&ql,  g_ql);
    cudaGetSymbolAddress((void**)&kh,  g_kh);
    cudaGetSymbolAddress((void**)&vh,  g_vh);
    cudaGetSymbolAddress((void**)&aoh, g_aoh);
    cudaGetSymbolAddress((void**)&aol, g_aol);
    cudaGetSymbolAddress((void**)&wqh, g_wqh);
    cudaGetSymbolAddress((void**)&wkh, g_wkh);
    cudaGetSymbolAddress((void**)&wvh, g_wvh);
    cudaGetSymbolAddress((void**)&woh, g_woh);

    cudaFuncSetAttribute(gemm_mma<0>, cudaFuncAttributeMaxDynamicSharedMemorySize,
                         GEMM_SMEM);
    cudaFuncSetAttribute(gemm_mma<1>, cudaFuncAttributeMaxDynamicSharedMemorySize,
                         GEMM_SMEM);
    cudaFuncSetAttribute(gemm_mma<2>, cudaFuncAttributeMaxDynamicSharedMemorySize,
                         GEMM_SMEM);
    cudaFuncSetAttribute(attn_mma, cudaFuncAttributeMaxDynamicSharedMemorySize,
                         ATT_SMEM);

    const int nx4 = MTOK * D / 4;
    const int nw4 = D * D / 4;
    split_hl<<<(nx4 + 255) / 256, 256>>>(x, xh, xl, nx4);
    conv_h<<<(nw4 + 255) / 256, 256>>>(Wq, wqh, nw4);
    conv_h<<<(nw4 + 255) / 256, 256>>>(Wk, wkh, nw4);
    conv_h<<<(nw4 + 255) / 256, 256>>>(Wv, wvh, nw4);
    conv_h<<<(nw4 + 255) / 256, 256>>>(Wo, woh, nw4);

    dim3 gg(D / BN, MTOK / BM);   // (8, 64)
    gemm_mma<1><<<gg, 256, GEMM_SMEM>>>(xh, xl, wqh, nullptr,
                                        nullptr, qh, ql);
    gemm_mma<2><<<gg, 256, GEMM_SMEM>>>(xh, xl, wkh, nullptr,
                                        nullptr, kh, nullptr);
    gemm_mma<2><<<gg, 256, GEMM_SMEM>>>(xh, xl, wvh, nullptr,
                                        nullptr, vh, nullptr);

    attn_mma<<<dim3(T / 128, H, B), 256, ATT_SMEM>>>(qh, ql, kh, vh, aoh, aol);

    gemm_mma<0><<<gg, 256, GEMM_SMEM>>>(aoh, aol, woh, bo,
                                        out, nullptr, nullptr);
}

// round 9
// speedup vs baseline: 6.0908x; 1.5799x over previous
#include <cuda_runtime.h>
#include <cuda_fp16.h>
#include <cstdint>

// ===========================================================================
// Problem constants
// ===========================================================================
constexpr int B = 4;
constexpr int T = 2048;
constexpr int D = 1024;
constexpr int H = 16;
constexpr int MTOK = B * T;          // 8192 token rows
using f16 = __half;

// ===========================================================================
// Scratch (allocation-free: __device__ globals) — all plain fp16 now
// ===========================================================================
__device__ f16 g_xh[(size_t)MTOK * D];
__device__ f16 g_qh[(size_t)MTOK * D];
__device__ f16 g_kh[(size_t)MTOK * D];
__device__ f16 g_vh[(size_t)MTOK * D];
__device__ f16 g_aoh[(size_t)MTOK * D];
__device__ f16 g_wqh[(size_t)D * D];
__device__ f16 g_wkh[(size_t)D * D];
__device__ f16 g_wvh[(size_t)D * D];
__device__ f16 g_woh[(size_t)D * D];

// ===========================================================================
// PTX helpers (sm_80-compatible; compute_100 PTX target — no tcgen05)
// ===========================================================================
__device__ __forceinline__ uint32_t cvta_smem(const void* p) {
    uint32_t a;
    asm("{ .reg .u64 t; cvta.to.shared.u64 t, %1; cvt.u32.u64 %0, t; }"
        : "=r"(a) : "l"(p));
    return a;
}

__device__ __forceinline__ void cp16(uint32_t dst, const void* src) {
    asm volatile("cp.async.cg.shared.global [%0], [%1], 16;"
                 :: "r"(dst), "l"(src));
}
#define CP_COMMIT() asm volatile("cp.async.commit_group;" ::: "memory")
template <int N>
__device__ __forceinline__ void cp_wait() {
    asm volatile("cp.async.wait_group %0;" :: "n"(N) : "memory");
}

__device__ __forceinline__ void ldm4(uint32_t* r, uint32_t a) {
    asm volatile("ldmatrix.sync.aligned.m8n8.x4.shared.b16 {%0,%1,%2,%3}, [%4];"
                 : "=r"(r[0]), "=r"(r[1]), "=r"(r[2]), "=r"(r[3]) : "r"(a));
}
__device__ __forceinline__ void ldm4t(uint32_t* r, uint32_t a) {
    asm volatile("ldmatrix.sync.aligned.m8n8.x4.trans.shared.b16 {%0,%1,%2,%3}, [%4];"
                 : "=r"(r[0]), "=r"(r[1]), "=r"(r[2]), "=r"(r[3]) : "r"(a));
}

__device__ __forceinline__ void mma_f16(float* c, const uint32_t* a,
                                        const uint32_t* b) {
    asm volatile(
        "mma.sync.aligned.m16n8k16.row.col.f32.f16.f16.f32 "
        "{%0,%1,%2,%3}, {%4,%5,%6,%7}, {%8,%9}, {%0,%1,%2,%3};"
        : "+f"(c[0]), "+f"(c[1]), "+f"(c[2]), "+f"(c[3])
        : "r"(a[0]), "r"(a[1]), "r"(a[2]), "r"(a[3]), "r"(b[0]), "r"(b[1]));
}

__device__ __forceinline__ float ex2f(float x) {
    float r;
    asm("ex2.approx.f32 %0, %1;" : "=f"(r) : "f"(x));
    return r;
}

// pack two fp32 into one fp16x2 register
__device__ __forceinline__ uint32_t pack_h2(float v0, float v1) {
    return ((uint32_t)__half_as_ushort(__float2half_rn(v1)) << 16) |
           __half_as_ushort(__float2half_rn(v0));
}

// ===========================================================================
// fp32 -> fp16 convert
// ===========================================================================
__global__ void __launch_bounds__(256) conv_h(const float* __restrict__ in,
                                              f16* __restrict__ hi, int n4) {
    int i = blockIdx.x * 256 + threadIdx.x;
    if (i >= n4) return;
    int idx = i << 2;
    float4 v = *(const float4*)(in + idx);
    *(uint32_t*)(hi + idx)     = pack_h2(v.x, v.y);
    *(uint32_t*)(hi + idx + 2) = pack_h2(v.z, v.w);
}

// ===========================================================================
// mma.sync fp16 GEMM: C[M,N] = A[M,K] * Bw[N,K]^T (+bias)
// Fixed: N = K = 1024. Tile 128x128, BK = 32, 8 warps of 64x32.
// OUT_MODE: 0 = fp32 + bias, 2 = fp16.
// ===========================================================================
constexpr int BM = 128, BN = 128, BK = 32;
constexpr int KPADB = 80;                       // bytes per smem row (40 elems)
constexpr int ATILE = BM * KPADB;               // 10240
constexpr int STAGE = 2 * ATILE;                // Ah, Bh = 20480
constexpr int GEMM_SMEM = 2 * STAGE;            // 40960
constexpr int NC = D / BK;                      // 32

template <int OUT_MODE>
__global__ void __launch_bounds__(256) gemm_mma(
    const f16* __restrict__ Ah, const f16* __restrict__ Bh,
    const float* __restrict__ bias,
    float* __restrict__ Cf, f16* __restrict__ Ch)
{
    extern __shared__ __align__(16) char smraw[];
    const uint32_t sb0 = cvta_smem(smraw);
    const int tid = threadIdx.x, lane = tid & 31, w = tid >> 5;
    const int wm = w >> 2, wn = w & 3;
    const int bm = blockIdx.y * BM, bn = blockIdx.x * BN;
    const int g = lane >> 3, tr = lane & 7;

    const char* pAh = (const char*)Ah;
    const char* pBh = (const char*)Bh;

    auto stage_load = [&](int c, int st) {
        const uint32_t sbs = sb0 + st * STAGE;
        const size_t koff = (size_t)c * (BK * 2);
#pragma unroll
        for (int i = 0; i < 2; i++) {
            int cid = tid + 256 * i;
            int r = cid >> 2, cc = cid & 3;
            uint32_t so = r * KPADB + cc * 16;
            size_t ga = (size_t)(bm + r) * 2048 + koff + cc * 16;
            size_t gb = (size_t)(bn + r) * 2048 + koff + cc * 16;
            cp16(sbs + so,         pAh + ga);
            cp16(sbs + ATILE + so, pBh + gb);
        }
        CP_COMMIT();
    };

    float acc[4][4][4];
#pragma unroll
    for (int i = 0; i < 4; i++)
#pragma unroll
        for (int j = 0; j < 4; j++)
#pragma unroll
            for (int e = 0; e < 4; e++) acc[i][j][e] = 0.f;

    stage_load(0, 0);

    for (int c = 0; c < NC; c++) {
        const int st = c & 1;
        if (c + 1 < NC) { stage_load(c + 1, st ^ 1); cp_wait<1>(); }
        else            { cp_wait<0>(); }
        __syncthreads();
        const uint32_t sA = sb0 + st * STAGE;
        const uint32_t sB = sA + ATILE;
#pragma unroll
        for (int ks = 0; ks < 2; ks++) {
            uint32_t a[4][4], bh[2][4];
            const uint32_t acol = (ks * 16 + (g >> 1) * 8) * 2;
            const uint32_t arow = (uint32_t)((g & 1) * 8 + tr);
            const uint32_t bcol = (ks * 16 + (g & 1) * 8) * 2;
            const uint32_t brow = (uint32_t)((g >> 1) * 8 + tr);
#pragma unroll
            for (int mi = 0; mi < 4; mi++)
                ldm4(a[mi], sA + (wm * 64 + mi * 16 + arow) * KPADB + acol);
#pragma unroll
            for (int nh = 0; nh < 2; nh++)
                ldm4(bh[nh], sB + (wn * 32 + nh * 16 + brow) * KPADB + bcol);
            // 16 independent accumulators
#pragma unroll
            for (int mi = 0; mi < 4; mi++)
#pragma unroll
                for (int ni = 0; ni < 4; ni++)
                    mma_f16(acc[mi][ni], a[mi], &bh[ni >> 1][(ni & 1) * 2]);
        }
        __syncthreads();
    }

    // Epilogue
    const int r0 = lane >> 2, c0 = (lane & 3) * 2;
#pragma unroll
    for (int mi = 0; mi < 4; mi++) {
        const int gr = bm + wm * 64 + mi * 16 + r0;
#pragma unroll
        for (int ni = 0; ni < 4; ni++) {
            const int gc = bn + wn * 32 + ni * 8 + c0;
            float v0 = acc[mi][ni][0], v1 = acc[mi][ni][1];
            float v2 = acc[mi][ni][2], v3 = acc[mi][ni][3];
            if (OUT_MODE == 2) {
                *(uint32_t*)(Ch + (size_t)gr * D + gc)       = pack_h2(v0, v1);
                *(uint32_t*)(Ch + (size_t)(gr + 8) * D + gc) = pack_h2(v2, v3);
            } else {
                float2 r4a = make_float2(v0 + bias[gc], v1 + bias[gc + 1]);
                float2 r4b = make_float2(v2 + bias[gc], v3 + bias[gc + 1]);
                *(float2*)(Cf + (size_t)gr * D + gc) = r4a;
                *(float2*)(Cf + (size_t)(gr + 8) * D + gc) = r4b;
            }
        }
    }
}

// ===========================================================================
// Flash attention (causal), fp16. CTA: 128 queries x 1 head, 8 warps x 16
// query rows. KV streamed 64 keys/step, double-buffered cp.async.
// P stays in registers (S cfrag -> PV afrag via fp16 pack).
// ===========================================================================
constexpr int APADB = 144;                       // 72 elems per smem row
constexpr int QTILE = 128 * APADB;               // 18432
constexpr int KTILE = 64 * APADB;                // 9216
constexpr int KVSTAGE = 2 * KTILE;               // 18432 (Kh + Vh)
constexpr int ATT_SMEM = QTILE + 2 * KVSTAGE;    // 55296

__global__ void __launch_bounds__(256) attn_mma(
    const f16* __restrict__ Qh, const f16* __restrict__ Kh,
    const f16* __restrict__ Vh, f16* __restrict__ AOh)
{
    extern __shared__ __align__(16) char smraw[];
    const uint32_t sb = cvta_smem(smraw);
    const uint32_t sQ = sb;
    const int qt = blockIdx.x, h = blockIdx.y, b = blockIdx.z;
    const int tid = threadIdx.x, lane = tid & 31, w = tid >> 5;
    const int g = lane >> 3, tr = lane & 7;
    const size_t tok0 = (size_t)(b * T + qt * 128);
    const size_t hoff = (size_t)h * 128;        // byte col offset of head

#pragma unroll
    for (int i = 0; i < 4; i++) {
        int cid = tid + 256 * i;
        int r = cid >> 3, cc = cid & 7;
        uint32_t so = r * APADB + cc * 16;
        size_t go = (tok0 + r) * 2048 + hoff + cc * 16;
        cp16(sQ + so, (const char*)Qh + go);
    }
    auto kv_load = [&](int j, int st) {
        uint32_t skv = sb + QTILE + st * KVSTAGE;
        size_t kt0 = (size_t)(b * T + j * 64);
#pragma unroll
        for (int i = 0; i < 2; i++) {
            int cid = tid + 256 * i;
            int r = cid >> 3, cc = cid & 7;
            uint32_t so = r * APADB + cc * 16;
            size_t go = (kt0 + r) * 2048 + hoff + cc * 16;
            cp16(skv + so,         (const char*)Kh + go);
            cp16(skv + KTILE + so, (const char*)Vh + go);
        }
        CP_COMMIT();
    };
    kv_load(0, 0);

    float accO[8][4];
#pragma unroll
    for (int f = 0; f < 8; f++)
#pragma unroll
        for (int e = 0; e < 4; e++) accO[f][e] = 0.f;
    float m0 = -1e30f, m1 = -1e30f, l0 = 0.f, l1 = 0.f;

    const int jmax = 2 * qt + 1;
    const int qg0 = qt * 128 + w * 16 + (lane >> 2);
    const float SCALE = 0.125f;
    const float L2E = 1.4426950408889634f;

    for (int j = 0; j <= jmax; j++) {
        const int st = j & 1;
        if (j < jmax) { kv_load(j + 1, st ^ 1); cp_wait<1>(); }
        else          { cp_wait<0>(); }
        __syncthreads();
        const uint32_t sK = sb + QTILE + st * KVSTAGE;
        const uint32_t sV = sK + KTILE;

        // ---- S = Q Kh^T (8-wide independent) ----
        float s[8][4];
#pragma unroll
        for (int f = 0; f < 8; f++)
#pragma unroll
            for (int e = 0; e < 4; e++) s[f][e] = 0.f;

        const uint32_t qrow = (uint32_t)(w * 16 + (g & 1) * 8 + tr);
        const uint32_t brow = (uint32_t)((g >> 1) * 8 + tr);
#pragma unroll
        for (int ks = 0; ks < 4; ks++) {
            uint32_t qh[4], kf[4][4];
            ldm4(qh, sQ + qrow * APADB + (ks * 16 + (g >> 1) * 8) * 2);
            const uint32_t bcol = (ks * 16 + (g & 1) * 8) * 2;
#pragma unroll
            for (int nh = 0; nh < 4; nh++)
                ldm4(kf[nh], sK + (nh * 16 + brow) * APADB + bcol);
#pragma unroll
            for (int nh = 0; nh < 4; nh++) {
                mma_f16(s[2 * nh],     qh, kf[nh]);
                mma_f16(s[2 * nh + 1], qh, kf[nh] + 2);
            }
        }

        // ---- scale + causal mask ----
        const bool need_mask = (j >= 2 * qt);
#pragma unroll
        for (int f = 0; f < 8; f++) {
            const int kgb = j * 64 + f * 8 + (lane & 3) * 2;
#pragma unroll
            for (int e = 0; e < 4; e++) {
                const int kg = kgb + (e & 1);
                const int qg = qg0 + (e >> 1) * 8;
                float v = s[f][e] * SCALE;
                if (need_mask && kg > qg) v = -1e30f;
                s[f][e] = v;
            }
        }

        // ---- online softmax (quad-wide reductions) ----
        float mx0 = -1e30f, mx1 = -1e30f;
#pragma unroll
        for (int f = 0; f < 8; f++) {
            mx0 = fmaxf(mx0, fmaxf(s[f][0], s[f][1]));
            mx1 = fmaxf(mx1, fmaxf(s[f][2], s[f][3]));
        }
        mx0 = fmaxf(mx0, __shfl_xor_sync(0xffffffffu, mx0, 1));
        mx0 = fmaxf(mx0, __shfl_xor_sync(0xffffffffu, mx0, 2));
        mx1 = fmaxf(mx1, __shfl_xor_sync(0xffffffffu, mx1, 1));
        mx1 = fmaxf(mx1, __shfl_xor_sync(0xffffffffu, mx1, 2));
        const float mn0 = fmaxf(m0, mx0);
        const float mn1 = fmaxf(m1, mx1);
        const float cr0 = ex2f((m0 - mn0) * L2E);
        const float cr1 = ex2f((m1 - mn1) * L2E);
        float sum0 = 0.f, sum1 = 0.f;
#pragma unroll
        for (int f = 0; f < 8; f++) {
            float p0 = ex2f((s[f][0] - mn0) * L2E);
            float p1 = ex2f((s[f][1] - mn0) * L2E);
            float p2 = ex2f((s[f][2] - mn1) * L2E);
            float p3 = ex2f((s[f][3] - mn1) * L2E);
            s[f][0] = p0; s[f][1] = p1; s[f][2] = p2; s[f][3] = p3;
            sum0 += p0 + p1;
            sum1 += p2 + p3;
        }
        sum0 += __shfl_xor_sync(0xffffffffu, sum0, 1);
        sum0 += __shfl_xor_sync(0xffffffffu, sum0, 2);
        sum1 += __shfl_xor_sync(0xffffffffu, sum1, 1);
        sum1 += __shfl_xor_sync(0xffffffffu, sum1, 2);
        l0 = l0 * cr0 + sum0;
        l1 = l1 * cr1 + sum1;
        m0 = mn0; m1 = mn1;
#pragma unroll
        for (int f = 0; f < 8; f++) {
            accO[f][0] *= cr0; accO[f][1] *= cr0;
            accO[f][2] *= cr1; accO[f][3] *= cr1;
        }

        // ---- O += P Vh (P packed fp16 in registers, 8-wide independent) ----
#pragma unroll
        for (int k2 = 0; k2 < 4; k2++) {
            uint32_t afh[4], vf[4][4];
            afh[0] = pack_h2(s[2 * k2][0],     s[2 * k2][1]);
            afh[1] = pack_h2(s[2 * k2][2],     s[2 * k2][3]);
            afh[2] = pack_h2(s[2 * k2 + 1][0], s[2 * k2 + 1][1]);
            afh[3] = pack_h2(s[2 * k2 + 1][2], s[2 * k2 + 1][3]);
            const uint32_t vrow = (uint32_t)(k2 * 16 + (g & 1) * 8 + tr);
#pragma unroll
            for (int db = 0; db < 4; db++)
                ldm4t(vf[db], sV + vrow * APADB + (db * 16 + (g >> 1) * 8) * 2);
#pragma unroll
            for (int db = 0; db < 4; db++) {
                mma_f16(accO[2 * db],     afh, vf[db]);
                mma_f16(accO[2 * db + 1], afh, vf[db] + 2);
            }
        }
        __syncthreads();   // protect KV stage before next prefetch overwrites
    }

    // ---- epilogue: normalize, fp16 store ----
    const float inv0 = 1.f / l0;
    const float inv1 = 1.f / l1;
    const size_t r0g = tok0 + w * 16 + (lane >> 2);
    const int c0 = (lane & 3) * 2;
#pragma unroll
    for (int f = 0; f < 8; f++) {
        const int gc = h * 64 + f * 8 + c0;
        *(uint32_t*)(AOh + r0g * D + gc) =
            pack_h2(accO[f][0] * inv0, accO[f][1] * inv0);
        *(uint32_t*)(AOh + (r0g + 8) * D + gc) =
            pack_h2(accO[f][2] * inv1, accO[f][3] * inv1);
    }
}

// ===========================================================================
extern "C" void kernel_launch(void* const* d_in, const int* in_sizes, int n_in,
                              void* d_out, int out_size)
{
    (void)in_sizes; (void)n_in; (void)out_size;
    const float* x  = (const float*)d_in[0];
    const float* Wq = (const float*)d_in[1];
    const float* Wk = (const float*)d_in[2];
    const float* Wv = (const float*)d_in[3];
    const float* Wo = (const float*)d_in[4];
    const float* bo = (const float*)d_in[5];
    float* out = (float*)d_out;

    f16 *xh, *qh, *kh, *vh, *aoh;
    f16 *wqh, *wkh, *wvh, *woh;
    cudaGetSymbolAddress((void**)&xh,  g_xh);
    cudaGetSymbolAddress((void**)&qh,  g_qh);
    cudaGetSymbolAddress((void**)&kh,  g_kh);
    cudaGetSymbolAddress((void**)&vh,  g_vh);
    cudaGetSymbolAddress((void**)&aoh, g_aoh);
    cudaGetSymbolAddress((void**)&wqh, g_wqh);
    cudaGetSymbolAddress((void**)&wkh, g_wkh);
    cudaGetSymbolAddress((void**)&wvh, g_wvh);
    cudaGetSymbolAddress((void**)&woh, g_woh);

    cudaFuncSetAttribute(gemm_mma<0>, cudaFuncAttributeMaxDynamicSharedMemorySize,
                         GEMM_SMEM);
    cudaFuncSetAttribute(gemm_mma<2>, cudaFuncAttributeMaxDynamicSharedMemorySize,
                         GEMM_SMEM);
    cudaFuncSetAttribute(attn_mma, cudaFuncAttributeMaxDynamicSharedMemorySize,
                         ATT_SMEM);

    const int nx4 = MTOK * D / 4;
    const int nw4 = D * D / 4;
    conv_h<<<(nx4 + 255) / 256, 256>>>(x,  xh,  nx4);
    conv_h<<<(nw4 + 255) / 256, 256>>>(Wq, wqh, nw4);
    conv_h<<<(nw4 + 255) / 256, 256>>>(Wk, wkh, nw4);
    conv_h<<<(nw4 + 255) / 256, 256>>>(Wv, wvh, nw4);
    conv_h<<<(nw4 + 255) / 256, 256>>>(Wo, woh, nw4);

    dim3 gg(D / BN, MTOK / BM);   // (8, 64)
    gemm_mma<2><<<gg, 256, GEMM_SMEM>>>(xh, wqh, nullptr, nullptr, qh);
    gemm_mma<2><<<gg, 256, GEMM_SMEM>>>(xh, wkh, nullptr, nullptr, kh);
    gemm_mma<2><<<gg, 256, GEMM_SMEM>>>(xh, wvh, nullptr, nullptr, vh);

    attn_mma<<<dim3(T / 128, H, B), 256, ATT_SMEM>>>(qh, kh, vh, aoh);

    gemm_mma<0><<<gg, 256, GEMM_SMEM>>>(aoh, woh, bo, out, nullptr);
}

// round 10
// speedup vs baseline: 6.5696x; 1.0786x over previous
#include <cuda_runtime.h>
#include <cuda_fp16.h>
#include <cstdint>

// ===========================================================================
// Problem constants
// ===========================================================================
constexpr int B = 4;
constexpr int T = 2048;
constexpr int D = 1024;
constexpr int H = 16;
constexpr int MTOK = B * T;          // 8192 token rows
using f16 = __half;

// ===========================================================================
// Scratch (allocation-free: __device__ globals) — all plain fp16
// ===========================================================================
__device__ f16 g_xh[(size_t)MTOK * D];
__device__ f16 g_qh[(size_t)MTOK * D];
__device__ f16 g_kh[(size_t)MTOK * D];
__device__ f16 g_vh[(size_t)MTOK * D];
__device__ f16 g_aoh[(size_t)MTOK * D];
__device__ f16 g_wqh[(size_t)D * D];
__device__ f16 g_wkh[(size_t)D * D];
__device__ f16 g_wvh[(size_t)D * D];
__device__ f16 g_woh[(size_t)D * D];

// ===========================================================================
// PTX helpers (sm_80-compatible; compute_100 PTX target — no tcgen05)
// ===========================================================================
__device__ __forceinline__ uint32_t cvta_smem(const void* p) {
    uint32_t a;
    asm("{ .reg .u64 t; cvta.to.shared.u64 t, %1; cvt.u32.u64 %0, t; }"
        : "=r"(a) : "l"(p));
    return a;
}

__device__ __forceinline__ void cp16(uint32_t dst, const void* src) {
    asm volatile("cp.async.cg.shared.global [%0], [%1], 16;"
                 :: "r"(dst), "l"(src));
}
#define CP_COMMIT() asm volatile("cp.async.commit_group;" ::: "memory")
template <int N>
__device__ __forceinline__ void cp_wait() {
    asm volatile("cp.async.wait_group %0;" :: "n"(N) : "memory");
}

__device__ __forceinline__ void ldm4(uint32_t* r, uint32_t a) {
    asm volatile("ldmatrix.sync.aligned.m8n8.x4.shared.b16 {%0,%1,%2,%3}, [%4];"
                 : "=r"(r[0]), "=r"(r[1]), "=r"(r[2]), "=r"(r[3]) : "r"(a));
}
__device__ __forceinline__ void ldm4t(uint32_t* r, uint32_t a) {
    asm volatile("ldmatrix.sync.aligned.m8n8.x4.trans.shared.b16 {%0,%1,%2,%3}, [%4];"
                 : "=r"(r[0]), "=r"(r[1]), "=r"(r[2]), "=r"(r[3]) : "r"(a));
}

__device__ __forceinline__ void mma_f16(float* c, const uint32_t* a,
                                        const uint32_t* b) {
    asm volatile(
        "mma.sync.aligned.m16n8k16.row.col.f32.f16.f16.f32 "
        "{%0,%1,%2,%3}, {%4,%5,%6,%7}, {%8,%9}, {%0,%1,%2,%3};"
        : "+f"(c[0]), "+f"(c[1]), "+f"(c[2]), "+f"(c[3])
        : "r"(a[0]), "r"(a[1]), "r"(a[2]), "r"(a[3]), "r"(b[0]), "r"(b[1]));
}

__device__ __forceinline__ float ex2f(float x) {
    float r;
    asm("ex2.approx.f32 %0, %1;" : "=f"(r) : "f"(x));
    return r;
}

// pack two fp32 into one fp16x2 register
__device__ __forceinline__ uint32_t pack_h2(float v0, float v1) {
    return ((uint32_t)__half_as_ushort(__float2half_rn(v1)) << 16) |
           __half_as_ushort(__float2half_rn(v0));
}

// ===========================================================================
// fp32 -> fp16 converts: x (single), weights (4 sources via blockIdx.y)
// ===========================================================================
__global__ void __launch_bounds__(256) conv_h(const float* __restrict__ in,
                                              f16* __restrict__ hi, int n4) {
    int i = blockIdx.x * 256 + threadIdx.x;
    if (i >= n4) return;
    int idx = i << 2;
    float4 v = *(const float4*)(in + idx);
    *(uint32_t*)(hi + idx)     = pack_h2(v.x, v.y);
    *(uint32_t*)(hi + idx + 2) = pack_h2(v.z, v.w);
}

__global__ void __launch_bounds__(256) conv_w4(
    const float* __restrict__ w0, const float* __restrict__ w1,
    const float* __restrict__ w2, const float* __restrict__ w3,
    f16* __restrict__ o0, f16* __restrict__ o1,
    f16* __restrict__ o2, f16* __restrict__ o3, int n4)
{
    int i = blockIdx.x * 256 + threadIdx.x;
    if (i >= n4) return;
    const float* in = (blockIdx.y == 0) ? w0 : (blockIdx.y == 1) ? w1
                    : (blockIdx.y == 2) ? w2 : w3;
    f16* hi = (blockIdx.y == 0) ? o0 : (blockIdx.y == 1) ? o1
            : (blockIdx.y == 2) ? o2 : o3;
    int idx = i << 2;
    float4 v = *(const float4*)(in + idx);
    *(uint32_t*)(hi + idx)     = pack_h2(v.x, v.y);
    *(uint32_t*)(hi + idx + 2) = pack_h2(v.z, v.w);
}

// ===========================================================================
// mma.sync fp16 GEMM core: C[M,N] = A[M,K] * Bw[N,K]^T (+bias)
// Fixed: N = K = 1024. Tile 128x128, BK = 32, 8 warps of 64x32.
// ===========================================================================
constexpr int BM = 128, BN = 128, BK = 32;
constexpr int KPADB = 80;                       // bytes per smem row (40 elems)
constexpr int ATILE = BM * KPADB;               // 10240
constexpr int STAGE = 2 * ATILE;                // Ah, Bh = 20480
constexpr int GEMM_SMEM = 2 * STAGE;            // 40960
constexpr int NC = D / BK;                      // 32

// OUT_MODE: 0 = fp32 + bias, 2 = fp16
template <int OUT_MODE>
__device__ __forceinline__ void gemm_body(
    const f16* __restrict__ Ah, const f16* __restrict__ Bh,
    const float* __restrict__ bias,
    float* __restrict__ Cf, f16* __restrict__ Ch, char* smraw)
{
    const uint32_t sb0 = cvta_smem(smraw);
    const int tid = threadIdx.x, lane = tid & 31, w = tid >> 5;
    const int wm = w >> 2, wn = w & 3;
    const int bm = blockIdx.y * BM, bn = blockIdx.x * BN;
    const int g = lane >> 3, tr = lane & 7;

    const char* pAh = (const char*)Ah;
    const char* pBh = (const char*)Bh;

    auto stage_load = [&](int c, int st) {
        const uint32_t sbs = sb0 + st * STAGE;
        const size_t koff = (size_t)c * (BK * 2);
#pragma unroll
        for (int i = 0; i < 2; i++) {
            int cid = tid + 256 * i;
            int r = cid >> 2, cc = cid & 3;
            uint32_t so = r * KPADB + cc * 16;
            size_t ga = (size_t)(bm + r) * 2048 + koff + cc * 16;
            size_t gb = (size_t)(bn + r) * 2048 + koff + cc * 16;
            cp16(sbs + so,         pAh + ga);
            cp16(sbs + ATILE + so, pBh + gb);
        }
        CP_COMMIT();
    };

    float acc[4][4][4];
#pragma unroll
    for (int i = 0; i < 4; i++)
#pragma unroll
        for (int j = 0; j < 4; j++)
#pragma unroll
            for (int e = 0; e < 4; e++) acc[i][j][e] = 0.f;

    stage_load(0, 0);

    for (int c = 0; c < NC; c++) {
        const int st = c & 1;
        if (c + 1 < NC) { stage_load(c + 1, st ^ 1); cp_wait<1>(); }
        else            { cp_wait<0>(); }
        __syncthreads();
        const uint32_t sA = sb0 + st * STAGE;
        const uint32_t sB = sA + ATILE;
#pragma unroll
        for (int ks = 0; ks < 2; ks++) {
            uint32_t a[4][4], bh[2][4];
            const uint32_t acol = (ks * 16 + (g >> 1) * 8) * 2;
            const uint32_t arow = (uint32_t)((g & 1) * 8 + tr);
            const uint32_t bcol = (ks * 16 + (g & 1) * 8) * 2;
            const uint32_t brow = (uint32_t)((g >> 1) * 8 + tr);
#pragma unroll
            for (int mi = 0; mi < 4; mi++)
                ldm4(a[mi], sA + (wm * 64 + mi * 16 + arow) * KPADB + acol);
#pragma unroll
            for (int nh = 0; nh < 2; nh++)
                ldm4(bh[nh], sB + (wn * 32 + nh * 16 + brow) * KPADB + bcol);
#pragma unroll
            for (int mi = 0; mi < 4; mi++)
#pragma unroll
                for (int ni = 0; ni < 4; ni++)
                    mma_f16(acc[mi][ni], a[mi], &bh[ni >> 1][(ni & 1) * 2]);
        }
        __syncthreads();
    }

    const int r0 = lane >> 2, c0 = (lane & 3) * 2;
#pragma unroll
    for (int mi = 0; mi < 4; mi++) {
        const int gr = bm + wm * 64 + mi * 16 + r0;
#pragma unroll
        for (int ni = 0; ni < 4; ni++) {
            const int gc = bn + wn * 32 + ni * 8 + c0;
            float v0 = acc[mi][ni][0], v1 = acc[mi][ni][1];
            float v2 = acc[mi][ni][2], v3 = acc[mi][ni][3];
            if (OUT_MODE == 2) {
                *(uint32_t*)(Ch + (size_t)gr * D + gc)       = pack_h2(v0, v1);
                *(uint32_t*)(Ch + (size_t)(gr + 8) * D + gc) = pack_h2(v2, v3);
            } else {
                float2 r4a = make_float2(v0 + bias[gc], v1 + bias[gc + 1]);
                float2 r4b = make_float2(v2 + bias[gc], v3 + bias[gc + 1]);
                *(float2*)(Cf + (size_t)gr * D + gc) = r4a;
                *(float2*)(Cf + (size_t)(gr + 8) * D + gc) = r4b;
            }
        }
    }
}

// Merged Q/K/V projection: one launch, grid.z selects {Wq->q, Wk->k, Wv->v}.
// Amortizes the 1.73-wave tail over 3x the work.
__global__ void __launch_bounds__(256) gemm_qkv(
    const f16* __restrict__ Ah,
    const f16* __restrict__ Wq, const f16* __restrict__ Wk,
    const f16* __restrict__ Wv,
    f16* __restrict__ Cq, f16* __restrict__ Ck, f16* __restrict__ Cv)
{
    extern __shared__ __align__(16) char smraw[];
    const f16* Bh = (blockIdx.z == 0) ? Wq : (blockIdx.z == 1) ? Wk : Wv;
    f16* Ch       = (blockIdx.z == 0) ? Cq : (blockIdx.z == 1) ? Ck : Cv;
    gemm_body<2>(Ah, Bh, nullptr, nullptr, Ch, smraw);
}

__global__ void __launch_bounds__(256) gemm_out(
    const f16* __restrict__ Ah, const f16* __restrict__ Bh,
    const float* __restrict__ bias, float* __restrict__ Cf)
{
    extern __shared__ __align__(16) char smraw[];
    gemm_body<0>(Ah, Bh, bias, Cf, nullptr, smraw);
}

// ===========================================================================
// Flash attention (causal), fp16. CTA: 128 queries x 1 head, 8 warps x 16
// query rows. KV streamed 64 keys/step, double-buffered cp.async.
// HEAVY-FIRST causal scheduling: qt = NQT-1 - blockIdx.x so the 32-step
// diagonal-heavy tiles launch in wave 1 (LPT makespan).
// ===========================================================================
constexpr int APADB = 144;                       // 72 elems per smem row
constexpr int QTILE = 128 * APADB;               // 18432
constexpr int KTILE = 64 * APADB;                // 9216
constexpr int KVSTAGE = 2 * KTILE;               // 18432 (Kh + Vh)
constexpr int ATT_SMEM = QTILE + 2 * KVSTAGE;    // 55296
constexpr int NQT = T / 128;                     // 16

__global__ void __launch_bounds__(256) attn_mma(
    const f16* __restrict__ Qh, const f16* __restrict__ Kh,
    const f16* __restrict__ Vh, f16* __restrict__ AOh)
{
    extern __shared__ __align__(16) char smraw[];
    const uint32_t sb = cvta_smem(smraw);
    const uint32_t sQ = sb;
    const int qt = NQT - 1 - blockIdx.x;          // heavy-first
    const int h = blockIdx.y, b = blockIdx.z;
    const int tid = threadIdx.x, lane = tid & 31, w = tid >> 5;
    const int g = lane >> 3, tr = lane & 7;
    const size_t tok0 = (size_t)(b * T + qt * 128);
    const size_t hoff = (size_t)h * 128;        // byte col offset of head

#pragma unroll
    for (int i = 0; i < 4; i++) {
        int cid = tid + 256 * i;
        int r = cid >> 3, cc = cid & 7;
        uint32_t so = r * APADB + cc * 16;
        size_t go = (tok0 + r) * 2048 + hoff + cc * 16;
        cp16(sQ + so, (const char*)Qh + go);
    }
    auto kv_load = [&](int j, int st) {
        uint32_t skv = sb + QTILE + st * KVSTAGE;
        size_t kt0 = (size_t)(b * T + j * 64);
#pragma unroll
        for (int i = 0; i < 2; i++) {
            int cid = tid + 256 * i;
            int r = cid >> 3, cc = cid & 7;
            uint32_t so = r * APADB + cc * 16;
            size_t go = (kt0 + r) * 2048 + hoff + cc * 16;
            cp16(skv + so,         (const char*)Kh + go);
            cp16(skv + KTILE + so, (const char*)Vh + go);
        }
        CP_COMMIT();
    };
    kv_load(0, 0);

    float accO[8][4];
#pragma unroll
    for (int f = 0; f < 8; f++)
#pragma unroll
        for (int e = 0; e < 4; e++) accO[f][e] = 0.f;
    float m0 = -1e30f, m1 = -1e30f, l0 = 0.f, l1 = 0.f;

    const int jmax = 2 * qt + 1;
    const int qg0 = qt * 128 + w * 16 + (lane >> 2);
    const float SCALE = 0.125f;
    const float L2E = 1.4426950408889634f;

    for (int j = 0; j <= jmax; j++) {
        const int st = j & 1;
        if (j < jmax) { kv_load(j + 1, st ^ 1); cp_wait<1>(); }
        else          { cp_wait<0>(); }
        __syncthreads();
        const uint32_t sK = sb + QTILE + st * KVSTAGE;
        const uint32_t sV = sK + KTILE;

        // ---- S = Q Kh^T (8-wide independent) ----
        float s[8][4];
#pragma unroll
        for (int f = 0; f < 8; f++)
#pragma unroll
            for (int e = 0; e < 4; e++) s[f][e] = 0.f;

        const uint32_t qrow = (uint32_t)(w * 16 + (g & 1) * 8 + tr);
        const uint32_t brow = (uint32_t)((g >> 1) * 8 + tr);
#pragma unroll
        for (int ks = 0; ks < 4; ks++) {
            uint32_t qh[4], kf[4][4];
            ldm4(qh, sQ + qrow * APADB + (ks * 16 + (g >> 1) * 8) * 2);
            const uint32_t bcol = (ks * 16 + (g & 1) * 8) * 2;
#pragma unroll
            for (int nh = 0; nh < 4; nh++)
                ldm4(kf[nh], sK + (nh * 16 + brow) * APADB + bcol);
#pragma unroll
            for (int nh = 0; nh < 4; nh++) {
                mma_f16(s[2 * nh],     qh, kf[nh]);
                mma_f16(s[2 * nh + 1], qh, kf[nh] + 2);
            }
        }

        // ---- scale + causal mask ----
        const bool need_mask = (j >= 2 * qt);
#pragma unroll
        for (int f = 0; f < 8; f++) {
            const int kgb = j * 64 + f * 8 + (lane & 3) * 2;
#pragma unroll
            for (int e = 0; e < 4; e++) {
                const int kg = kgb + (e & 1);
                const int qg = qg0 + (e >> 1) * 8;
                float v = s[f][e] * SCALE;
                if (need_mask && kg > qg) v = -1e30f;
                s[f][e] = v;
            }
        }

        // ---- online softmax (quad-wide reductions) ----
        float mx0 = -1e30f, mx1 = -1e30f;
#pragma unroll
        for (int f = 0; f < 8; f++) {
            mx0 = fmaxf(mx0, fmaxf(s[f][0], s[f][1]));
            mx1 = fmaxf(mx1, fmaxf(s[f][2], s[f][3]));
        }
        mx0 = fmaxf(mx0, __shfl_xor_sync(0xffffffffu, mx0, 1));
        mx0 = fmaxf(mx0, __shfl_xor_sync(0xffffffffu, mx0, 2));
        mx1 = fmaxf(mx1, __shfl_xor_sync(0xffffffffu, mx1, 1));
        mx1 = fmaxf(mx1, __shfl_xor_sync(0xffffffffu, mx1, 2));
        const float mn0 = fmaxf(m0, mx0);
        const float mn1 = fmaxf(m1, mx1);
        const float cr0 = ex2f((m0 - mn0) * L2E);
        const float cr1 = ex2f((m1 - mn1) * L2E);
        float sum0 = 0.f, sum1 = 0.f;
#pragma unroll
        for (int f = 0; f < 8; f++) {
            float p0 = ex2f((s[f][0] - mn0) * L2E);
            float p1 = ex2f((s[f][1] - mn0) * L2E);
            float p2 = ex2f((s[f][2] - mn1) * L2E);
            float p3 = ex2f((s[f][3] - mn1) * L2E);
            s[f][0] = p0; s[f][1] = p1; s[f][2] = p2; s[f][3] = p3;
            sum0 += p0 + p1;
            sum1 += p2 + p3;
        }
        sum0 += __shfl_xor_sync(0xffffffffu, sum0, 1);
        sum0 += __shfl_xor_sync(0xffffffffu, sum0, 2);
        sum1 += __shfl_xor_sync(0xffffffffu, sum1, 1);
        sum1 += __shfl_xor_sync(0xffffffffu, sum1, 2);
        l0 = l0 * cr0 + sum0;
        l1 = l1 * cr1 + sum1;
        m0 = mn0; m1 = mn1;
#pragma unroll
        for (int f = 0; f < 8; f++) {
            accO[f][0] *= cr0; accO[f][1] *= cr0;
            accO[f][2] *= cr1; accO[f][3] *= cr1;
        }

        // ---- O += P Vh (P packed fp16 in registers, 8-wide independent) ----
#pragma unroll
        for (int k2 = 0; k2 < 4; k2++) {
            uint32_t afh[4], vf[4][4];
            afh[0] = pack_h2(s[2 * k2][0],     s[2 * k2][1]);
            afh[1] = pack_h2(s[2 * k2][2],     s[2 * k2][3]);
            afh[2] = pack_h2(s[2 * k2 + 1][0], s[2 * k2 + 1][1]);
            afh[3] = pack_h2(s[2 * k2 + 1][2], s[2 * k2 + 1][3]);
            const uint32_t vrow = (uint32_t)(k2 * 16 + (g & 1) * 8 + tr);
#pragma unroll
            for (int db = 0; db < 4; db++)
                ldm4t(vf[db], sV + vrow * APADB + (db * 16 + (g >> 1) * 8) * 2);
#pragma unroll
            for (int db = 0; db < 4; db++) {
                mma_f16(accO[2 * db],     afh, vf[db]);
                mma_f16(accO[2 * db + 1], afh, vf[db] + 2);
            }
        }
        __syncthreads();   // protect KV stage before next prefetch overwrites
    }

    // ---- epilogue: normalize, fp16 store ----
    const float inv0 = 1.f / l0;
    const float inv1 = 1.f / l1;
    const size_t r0g = tok0 + w * 16 + (lane >> 2);
    const int c0 = (lane & 3) * 2;
#pragma unroll
    for (int f = 0; f < 8; f++) {
        const int gc = h * 64 + f * 8 + c0;
        *(uint32_t*)(AOh + r0g * D + gc) =
            pack_h2(accO[f][0] * inv0, accO[f][1] * inv0);
        *(uint32_t*)(AOh + (r0g + 8) * D + gc) =
            pack_h2(accO[f][2] * inv1, accO[f][3] * inv1);
    }
}

// ===========================================================================
extern "C" void kernel_launch(void* const* d_in, const int* in_sizes, int n_in,
                              void* d_out, int out_size)
{
    (void)in_sizes; (void)n_in; (void)out_size;
    const float* x  = (const float*)d_in[0];
    const float* Wq = (const float*)d_in[1];
    const float* Wk = (const float*)d_in[2];
    const float* Wv = (const float*)d_in[3];
    const float* Wo = (const float*)d_in[4];
    const float* bo = (const float*)d_in[5];
    float* out = (float*)d_out;

    f16 *xh, *qh, *kh, *vh, *aoh;
    f16 *wqh, *wkh, *wvh, *woh;
    cudaGetSymbolAddress((void**)&xh,  g_xh);
    cudaGetSymbolAddress((void**)&qh,  g_qh);
    cudaGetSymbolAddress((void**)&kh,  g_kh);
    cudaGetSymbolAddress((void**)&vh,  g_vh);
    cudaGetSymbolAddress((void**)&aoh, g_aoh);
    cudaGetSymbolAddress((void**)&wqh, g_wqh);
    cudaGetSymbolAddress((void**)&wkh, g_wkh);
    cudaGetSymbolAddress((void**)&wvh, g_wvh);
    cudaGetSymbolAddress((void**)&woh, g_woh);

    cudaFuncSetAttribute(gemm_qkv, cudaFuncAttributeMaxDynamicSharedMemorySize,
                         GEMM_SMEM);
    cudaFuncSetAttribute(gemm_out, cudaFuncAttributeMaxDynamicSharedMemorySize,
                         GEMM_SMEM);
    cudaFuncSetAttribute(attn_mma, cudaFuncAttributeMaxDynamicSharedMemorySize,
                         ATT_SMEM);

    const int nx4 = MTOK * D / 4;
    const int nw4 = D * D / 4;
    conv_h<<<(nx4 + 255) / 256, 256>>>(x, xh, nx4);
    conv_w4<<<dim3((nw4 + 255) / 256, 4), 256>>>(Wq, Wk, Wv, Wo,
                                                 wqh, wkh, wvh, woh, nw4);

    // Q, K, V projections in ONE launch (grid.z selects output)
    gemm_qkv<<<dim3(D / BN, MTOK / BM, 3), 256, GEMM_SMEM>>>(
        xh, wqh, wkh, wvh, qh, kh, vh);

    attn_mma<<<dim3(NQT, H, B), 256, ATT_SMEM>>>(qh, kh, vh, aoh);

    gemm_out<<<dim3(D / BN, MTOK / BM), 256, GEMM_SMEM>>>(aoh, woh, bo, out);
}